// round 8
// baseline (speedup 1.0000x reference)
#include <cuda_runtime.h>
#include <cstdint>

// ---------------- scratch (device globals; no allocation allowed) ----------
__device__ float g_r1b [1179648];  // [2][64][96][96]  after refine conv1
__device__ float g_r2b [1179648];  // [2][64][96][96]  query features q
__device__ float g_t48 [294912];   // [2][64][48][48]  bn(conv1x1(c2))
__device__ float g_c2r [1179648];  // [2][64][96][96]  relu(upsample(t48)) = keys
__device__ float g_attb[165888];   // [2][9][9216]     softmax attention
__device__ float g_pool[204800];   // [2][2048*50]     pooled x
__device__ float g_ppol[51200];    // [2][512*50]      relu(bn(1x1 conv)) of pooled
__device__ float g_psp [18874368]; // [2][4096][48][48] concat psp features
__device__ float g_out5[2359296];  // [2][512][48][48] conv5 output
__device__ float g_z48 [271872];   // [2][59][48][48]  conv6(out) (no bias)
__device__ float g_z96 [1087488];  // [2][59][96][96]  upsampled z

// ======================= baseline-ISA helpers ==============================
__device__ __forceinline__ uint32_t smem_u32(const void* p) {
    uint32_t a;
    asm("{ .reg .u64 t; cvta.to.shared.u64 t, %1; cvt.u32.u64 %0, t; }" : "=r"(a) : "l"(p));
    return a;
}
__device__ __forceinline__ void cp_async16(uint32_t dst, const void* src) {
    asm volatile("cp.async.ca.shared.global [%0], [%1], 16;" :: "r"(dst), "l"(src));
}
#define CP_COMMIT() asm volatile("cp.async.commit_group;" ::: "memory")
#define CP_WAIT1()  asm volatile("cp.async.wait_group 1;" ::: "memory")

__device__ __forceinline__ void mma16n8k8(float* c, const uint32_t* a, const uint32_t* b)
{
    asm volatile(
        "mma.sync.aligned.m16n8k8.row.col.f32.tf32.tf32.f32 "
        "{%0,%1,%2,%3}, {%4,%5,%6,%7}, {%8,%9}, {%0,%1,%2,%3};"
        : "+f"(c[0]), "+f"(c[1]), "+f"(c[2]), "+f"(c[3])
        : "r"(a[0]), "r"(a[1]), "r"(a[2]), "r"(a[3]), "r"(b[0]), "r"(b[1]));
}

// ===========================================================================
// conv5 via tf32 mma.sync, implicit im2col, 3-stage cp.async pipeline.
//   Out[m,p] = BNReLU( sum_k W[m,k] * B[p,k] ),  k = cin*9 + tap (3x3, pad 1)
//   M=512, N=2304 px, K=36864. CTA tile 128x128, KC=32, 8 warps (warp 32x64).
//   A smem: [m][k] stride 36 (cp.async, conflict-free frags: bank=4*gid+tig)
//   B smem: [k][n] stride 136 (gather via regs, conflict-free frags)
// ===========================================================================
#define KC   32
#define NCH  1152   // 36864 / 32
#define ASZ  4608   // 128 * 36 floats
#define BSZ  4352   // 32 * 136 floats

__global__ void __launch_bounds__(256, 1)
c5_mma_kernel(const float* __restrict__ Aw, const float* __restrict__ psp,
              const float* __restrict__ bnp, float* __restrict__ Out)
{
    extern __shared__ float sm[];
    float* Ast[3] = { sm, sm + ASZ, sm + 2 * ASZ };
    float* Bst[3] = { sm + 3 * ASZ, sm + 3 * ASZ + BSZ, sm + 3 * ASZ + 2 * BSZ };

    const int t    = threadIdx.x;
    const int wid  = t >> 5;
    const int lane = t & 31;
    const int gid  = lane >> 2;
    const int tig  = lane & 3;
    const int wm   = (wid & 3) * 32;
    const int wn   = (wid >> 2) * 64;

    const int img = blockIdx.z;
    const int bm  = blockIdx.y * 128;
    const int bp0 = blockIdx.x * 128;
    const float* Bn = psp + (long)img * 4096 * 2304;

    // A cp.async geometry: 4 segments of 16B per thread (1024 total)
    int a_row[4], a_seg[4];
    #pragma unroll
    for (int i = 0; i < 4; i++) { a_row[i] = (t * 4 + i) >> 3; a_seg[i] = (t * 4 + i) & 7; }

    // B loader geometry: 16 consecutive pixels at one k-row
    const int b_k  = t >> 3;
    const int b_n0 = (t & 7) * 16;
    const int pg0  = bp0 + b_n0;
    const int py0  = pg0 / 48;
    const int px0  = pg0 - py0 * 48;

    float brv[16];

    auto cpA = [&](int k0, float* Abuf) {
        #pragma unroll
        for (int i = 0; i < 4; i++) {
            uint32_t dst = smem_u32(Abuf + a_row[i] * 36 + a_seg[i] * 4);
            cp_async16(dst, Aw + (long)(bm + a_row[i]) * 36864 + k0 + a_seg[i] * 4);
        }
    };
    auto fetchB = [&](int k0) {
        int k   = k0 + b_k;
        int cin = k / 9;
        int tap = k - cin * 9;
        int dy  = tap / 3;
        int dx  = tap - dy * 3;
        int y   = py0 + dy - 1;
        bool vy = (unsigned)y < 48u;
        int  xb = px0 + dx - 1;
        const float* bp = Bn + (long)cin * 2304 + y * 48 + xb;
        #pragma unroll
        for (int j = 0; j < 16; j++) {
            int x = xb + j;
            brv[j] = (vy && (unsigned)x < 48u) ? __ldg(bp + j) : 0.f;
        }
    };
    auto stsB = [&](float* Bbuf) {
        #pragma unroll
        for (int j4 = 0; j4 < 4; j4++)
            *reinterpret_cast<float4*>(Bbuf + b_k * 136 + b_n0 + j4 * 4) =
                make_float4(brv[j4 * 4], brv[j4 * 4 + 1], brv[j4 * 4 + 2], brv[j4 * 4 + 3]);
    };

    float acc[2][8][4];
    #pragma unroll
    for (int mt = 0; mt < 2; mt++)
        #pragma unroll
        for (int nt = 0; nt < 8; nt++)
            #pragma unroll
            for (int i = 0; i < 4; i++) acc[mt][nt][i] = 0.f;

    // prologue: A(0), A(1) async; B(0) stored; B(1) in regs
    cpA(0, Ast[0]); CP_COMMIT();
    cpA(KC, Ast[1]); CP_COMMIT();
    fetchB(0);
    stsB(Bst[0]);
    fetchB(KC);
    CP_WAIT1();            // A(0) arrived
    __syncthreads();

    for (int it = 0; it < NCH; it++) {
        const int cur = it % 3;
        if (it + 1 < NCH) stsB(Bst[(it + 1) % 3]);      // B(it+1) from regs
        if (it + 2 < NCH) cpA((it + 2) * KC, Ast[(it + 2) % 3]);
        CP_COMMIT();                                     // one group per iter
        if (it + 2 < NCH) fetchB((it + 2) * KC);         // B(it+2) -> regs

        const float* A = Ast[cur];
        const float* B = Bst[cur];
        #pragma unroll
        for (int s = 0; s < 4; s++) {
            uint32_t af[2][4];
            uint32_t bf[8][2];
            #pragma unroll
            for (int mt = 0; mt < 2; mt++) {
                const float* ap = A + (wm + mt * 16 + gid) * 36 + s * 8 + tig;
                af[mt][0] = __float_as_uint(ap[0]);
                af[mt][1] = __float_as_uint(ap[8 * 36]);
                af[mt][2] = __float_as_uint(ap[4]);
                af[mt][3] = __float_as_uint(ap[8 * 36 + 4]);
            }
            #pragma unroll
            for (int nt = 0; nt < 8; nt++) {
                const float* bp = B + (s * 8 + tig) * 136 + wn + nt * 8 + gid;
                bf[nt][0] = __float_as_uint(bp[0]);
                bf[nt][1] = __float_as_uint(bp[4 * 136]);
            }
            #pragma unroll
            for (int mt = 0; mt < 2; mt++)
                #pragma unroll
                for (int nt = 0; nt < 8; nt++)
                    mma16n8k8(acc[mt][nt], af[mt], bf[nt]);
        }
        CP_WAIT1();                                      // A(it+1) arrived
        __syncthreads();
    }

    // epilogue: BN + ReLU
    #pragma unroll
    for (int mt = 0; mt < 2; mt++) {
        const int m0 = bm + wm + mt * 16 + gid;
        #pragma unroll
        for (int half = 0; half < 2; half++) {
            const int m = m0 + half * 8;
            const float g  = bnp[m], be = bnp[512 + m];
            const float mu = bnp[1024 + m], va = bnp[1536 + m];
            const float scale = g * rsqrtf(va + 1e-5f);
            const float shift = be - mu * scale;
            float* On = Out + ((long)img * 512 + m) * 2304 + bp0 + wn + tig * 2;
            #pragma unroll
            for (int nt = 0; nt < 8; nt++) {
                float2 v;
                v.x = fmaxf(fmaf(acc[mt][nt][half * 2],     scale, shift), 0.f);
                v.y = fmaxf(fmaf(acc[mt][nt][half * 2 + 1], scale, shift), 0.f);
                *reinterpret_cast<float2*>(On + nt * 8) = v;
            }
        }
    }
}

// ================= fp32 SGEMM (small convs) ================================
template<int TM, int DIL, bool BN, bool RELU, bool MCHECK, bool NCHECK>
__global__ void __launch_bounds__((TM/8)*16, 1)
gemm_conv(const float* __restrict__ A, const float* __restrict__ Bin,
          const float* __restrict__ bnp, float* __restrict__ Out,
          int M, int K, int H, int W, int Npix,
          long inStride, long outStride)
{
    constexpr int TN   = 128;
    constexpr int NT   = (TM / 8) * (TN / 8);
    constexpr int BVEC = (NT == 256) ? 4 : 8;

    __shared__ float As_[2][8][TM];
    __shared__ float Bs_[2][8][TN];

    const int tid = threadIdx.x;
    const int img = blockIdx.z;
    const float* Bn = Bin + (long)img * inStride;
    float*       On = Out + (long)img * outStride;
    const int bm  = blockIdx.y * TM;
    const int bp0 = blockIdx.x * TN;
    const int tr  = tid / 16;
    const int tc  = tid % 16;

    const int am = tid >> 1;
    const int ak = (tid & 1) * 4;
    const int bk = tid / (TN / BVEC);
    const int bp = (tid % (TN / BVEC)) * BVEC;

    float4 aReg;
    float  bReg[BVEC];

    auto fetch = [&](int k0) {
        int m = bm + am;
        if (!MCHECK || m < M)
            aReg = *reinterpret_cast<const float4*>(A + (long)m * K + k0 + ak);
        else
            aReg = make_float4(0.f, 0.f, 0.f, 0.f);
        int k = k0 + bk;
        if (DIL == 0) {
            const float* row = Bn + (long)k * Npix;
            if (!NCHECK) {
                #pragma unroll
                for (int j = 0; j < BVEC; j += 4) {
                    float4 v = *reinterpret_cast<const float4*>(row + bp0 + bp + j);
                    bReg[j] = v.x; bReg[j+1] = v.y; bReg[j+2] = v.z; bReg[j+3] = v.w;
                }
            } else {
                #pragma unroll
                for (int j = 0; j < BVEC; j++) {
                    int p = bp0 + bp + j;
                    bReg[j] = (p < Npix) ? row[p] : 0.f;
                }
            }
        } else {
            int cin = k / 9;
            int tap = k - cin * 9;
            int oy  = (tap / 3 - 1) * DIL;
            int ox  = (tap % 3 - 1) * DIL;
            const float* src = Bn + (long)cin * (H * W);
            #pragma unroll
            for (int j = 0; j < BVEC; j++) {
                int p  = bp0 + bp + j;
                int py = p / W;
                int px = p - py * W;
                int y  = py + oy;
                int x  = px + ox;
                bReg[j] = ((unsigned)y < (unsigned)H && (unsigned)x < (unsigned)W)
                          ? src[y * W + x] : 0.f;
            }
        }
    };
    auto put = [&](int buf) {
        As_[buf][ak + 0][am] = aReg.x;
        As_[buf][ak + 1][am] = aReg.y;
        As_[buf][ak + 2][am] = aReg.z;
        As_[buf][ak + 3][am] = aReg.w;
        #pragma unroll
        for (int j = 0; j < BVEC; j++) Bs_[buf][bk][bp + j] = bReg[j];
    };

    float acc[8][8];
    #pragma unroll
    for (int i = 0; i < 8; i++)
        #pragma unroll
        for (int j = 0; j < 8; j++) acc[i][j] = 0.f;

    fetch(0);
    put(0);
    __syncthreads();

    const int nK = K / 8;
    int buf = 0;
    for (int it = 0; it < nK; it++) {
        if (it + 1 < nK) fetch((it + 1) * 8);
        #pragma unroll
        for (int kk = 0; kk < 8; kk++) {
            float4 a0 = *reinterpret_cast<const float4*>(&As_[buf][kk][tr * 8]);
            float4 a1 = *reinterpret_cast<const float4*>(&As_[buf][kk][tr * 8 + 4]);
            float4 b0 = *reinterpret_cast<const float4*>(&Bs_[buf][kk][tc * 8]);
            float4 b1 = *reinterpret_cast<const float4*>(&Bs_[buf][kk][tc * 8 + 4]);
            float av[8] = {a0.x, a0.y, a0.z, a0.w, a1.x, a1.y, a1.z, a1.w};
            float bv[8] = {b0.x, b0.y, b0.z, b0.w, b1.x, b1.y, b1.z, b1.w};
            #pragma unroll
            for (int i = 0; i < 8; i++)
                #pragma unroll
                for (int j = 0; j < 8; j++)
                    acc[i][j] = fmaf(av[i], bv[j], acc[i][j]);
        }
        if (it + 1 < nK) put(buf ^ 1);
        __syncthreads();
        buf ^= 1;
    }

    #pragma unroll
    for (int i = 0; i < 8; i++) {
        int m = bm + tr * 8 + i;
        if (MCHECK && m >= M) continue;
        float scale = 1.f, shift = 0.f;
        if (BN) {
            float g  = bnp[m];
            float be = bnp[M + m];
            float mu = bnp[2 * M + m];
            float va = bnp[3 * M + m];
            scale = g * rsqrtf(va + 1e-5f);
            shift = be - mu * scale;
        }
        #pragma unroll
        for (int j = 0; j < 8; j++) {
            int p = bp0 + tc * 8 + j;
            if (NCHECK && p >= Npix) continue;
            float v = acc[i][j];
            if (BN)   v = fmaf(v, scale, shift);
            if (RELU) v = fmaxf(v, 0.f);
            On[(long)m * Npix + p] = v;
        }
    }
}

// -------- adaptive avg pool of x at scales 1,2,3,6 -------------------------
__global__ void pool_kernel(const float* __restrict__ x, float* __restrict__ pool)
{
    __shared__ float sm[2304];
    const int cin = blockIdx.x;
    const int n   = blockIdx.y;
    const float* src = x + ((long)n * 2048 + cin) * 2304;
    for (int i = threadIdx.x; i < 2304; i += blockDim.x) sm[i] = src[i];
    __syncthreads();
    int r = threadIdx.x;
    if (r < 50) {
        int sc, pi;
        if      (r < 1)  { sc = 0; pi = r; }
        else if (r < 5)  { sc = 1; pi = r - 1; }
        else if (r < 14) { sc = 2; pi = r - 5; }
        else             { sc = 3; pi = r - 14; }
        const int sides[4] = {1, 2, 3, 6};
        const int inoff[4] = {0, 2048, 10240, 28672};
        int side = sides[sc];
        int iy = pi / side, ix = pi % side;
        int bs = 48 / side;
        float s = 0.f;
        for (int yy = iy * bs; yy < (iy + 1) * bs; yy++)
            for (int xx = ix * bs; xx < (ix + 1) * bs; xx++)
                s += sm[yy * 48 + xx];
        pool[(long)n * 102400 + inoff[sc] + cin * (side * side) + pi] = s / (float)(bs * bs);
    }
}

struct PoolWArgs { const float* w[4]; const float* bn[4]; };

__global__ void pooled_conv_kernel(PoolWArgs args, const float* __restrict__ pool,
                                   float* __restrict__ ppool)
{
    int gw   = (blockIdx.x * blockDim.x + threadIdx.x) >> 5;
    int lane = threadIdx.x & 31;
    if (gw >= 51200) return;
    int n  = gw / 25600;
    int t  = gw % 25600;
    int pg = t / 512;
    int co = t % 512;
    int sc, pi;
    if      (pg < 1)  { sc = 0; pi = pg; }
    else if (pg < 5)  { sc = 1; pi = pg - 1; }
    else if (pg < 14) { sc = 2; pi = pg - 5; }
    else              { sc = 3; pi = pg - 14; }
    const int ssq[4]    = {1, 4, 9, 36};
    const int inoff[4]  = {0, 2048, 10240, 28672};
    const int outoff[4] = {0, 512, 2560, 7168};
    const float* w  = args.w[sc] + (long)co * 2048;
    const float* pb = pool + (long)n * 102400 + inoff[sc] + pi;
    int stride = ssq[sc];
    float acc = 0.f;
    for (int c = lane; c < 2048; c += 32)
        acc = fmaf(w[c], pb[(long)c * stride], acc);
    #pragma unroll
    for (int s = 16; s; s >>= 1) acc += __shfl_xor_sync(0xffffffffu, acc, s);
    if (lane == 0) {
        const float* bnp = args.bn[sc];
        float scale = bnp[co] * rsqrtf(bnp[1536 + co] + 1e-5f);
        float v = fmaf(acc, scale, bnp[512 + co] - bnp[1024 + co] * scale);
        ppool[(long)n * 25600 + outoff[sc] + co * stride + pi] = fmaxf(v, 0.f);
    }
}

__global__ void psp_assemble(const float* __restrict__ x, const float* __restrict__ ppool,
                             float* __restrict__ psp)
{
    long idx = (long)blockIdx.x * 256 + threadIdx.x;
    if (idx >= 18874368L) return;
    int p = (int)(idx % 2304);
    long t = idx / 2304;
    int c = (int)(t % 4096);
    int n = (int)(t / 4096);
    float v;
    if (c < 2048) {
        v = x[((long)n * 2048 + c) * 2304 + p];
    } else {
        int sc = (c - 2048) >> 9;
        int cc = (c - 2048) & 511;
        const int sides[4]  = {1, 2, 3, 6};
        const int outoff[4] = {0, 512, 2560, 7168};
        int s = sides[sc];
        const float* f = ppool + (long)n * 25600 + outoff[sc] + cc * s * s;
        if (s == 1) {
            v = f[0];
        } else {
            int y = p / 48, xx = p % 48;
            float ratio = (float)(s - 1) / 47.0f;
            float sy = y * ratio, sx = xx * ratio;
            int y0 = (int)sy, x0 = (int)sx;
            if (y0 > s - 1) y0 = s - 1;
            if (x0 > s - 1) x0 = s - 1;
            int y1 = min(y0 + 1, s - 1), x1 = min(x0 + 1, s - 1);
            float wy = sy - y0, wx = sx - x0;
            float r0 = f[y0 * s + x0] * (1.f - wx) + f[y0 * s + x1] * wx;
            float r1 = f[y1 * s + x0] * (1.f - wx) + f[y1 * s + x1] * wx;
            v = r0 * (1.f - wy) + r1 * wy;
        }
    }
    psp[idx] = v;
}

template<bool RELU>
__global__ void ups48to96(const float* __restrict__ in, float* __restrict__ out, int total)
{
    int idx = blockIdx.x * 256 + threadIdx.x;
    if (idx >= total) return;
    int p  = idx % 9216;
    int ch = idx / 9216;
    int y = p / 96, x = p % 96;
    const float r = 47.0f / 95.0f;
    float sy = y * r, sx = x * r;
    int y0 = (int)sy, x0 = (int)sx;
    if (y0 > 47) y0 = 47;
    if (x0 > 47) x0 = 47;
    int y1 = min(y0 + 1, 47), x1 = min(x0 + 1, 47);
    float wy = sy - y0, wx = sx - x0;
    const float* f = in + (long)ch * 2304;
    float v0 = f[y0 * 48 + x0] * (1.f - wx) + f[y0 * 48 + x1] * wx;
    float v1 = f[y1 * 48 + x0] * (1.f - wx) + f[y1 * 48 + x1] * wx;
    float v  = v0 * (1.f - wy) + v1 * wy;
    if (RELU) v = fmaxf(v, 0.f);
    out[idx] = v;
}

__global__ void att_kernel(const float* __restrict__ q, const float* __restrict__ kf,
                           float* __restrict__ att)
{
    int p = blockIdx.x * 256 + threadIdx.x;
    int n = blockIdx.y;
    if (p >= 9216) return;
    int y = p / 96, x = p % 96;
    int   offs[9];
    bool  valid[9];
    #pragma unroll
    for (int k = 0; k < 9; k++) {
        int yy = y + (k / 3 - 1) * 2;
        int xx = x + (k % 3 - 1) * 2;
        valid[k] = ((unsigned)yy < 96u) && ((unsigned)xx < 96u);
        offs[k]  = valid[k] ? yy * 96 + xx : 0;
    }
    float e[9];
    #pragma unroll
    for (int k = 0; k < 9; k++) e[k] = 0.f;
    const float* qn = q  + (long)n * 64 * 9216;
    const float* kn = kf + (long)n * 64 * 9216;
    for (int c = 0; c < 64; c++) {
        float qv = qn[c * 9216 + p];
        const float* base = kn + c * 9216;
        #pragma unroll
        for (int k = 0; k < 9; k++) {
            float kv = valid[k] ? base[offs[k]] : 0.f;
            e[k] = fmaf(qv, kv, e[k]);
        }
    }
    float mx = e[0];
    #pragma unroll
    for (int k = 1; k < 9; k++) mx = fmaxf(mx, e[k]);
    float sum = 0.f;
    #pragma unroll
    for (int k = 0; k < 9; k++) { e[k] = __expf(e[k] - mx); sum += e[k]; }
    float inv = 1.f / sum;
    #pragma unroll
    for (int k = 0; k < 9; k++)
        att[(long)n * 82944 + k * 9216 + p] = e[k] * inv;
}

__global__ void final_kernel(const float* __restrict__ att, const float* __restrict__ z,
                             const float* __restrict__ bias, float* __restrict__ out)
{
    int p = blockIdx.x * 256 + threadIdx.x;
    int o = blockIdx.y;
    int n = blockIdx.z;
    if (p >= 9216) return;
    int y = p / 96, x = p % 96;
    const float* zr = z   + ((long)n * 59 + o) * 9216;
    const float* an = att + (long)n * 82944;
    float acc = bias[o];
    #pragma unroll
    for (int k = 0; k < 9; k++) {
        int yy = y + (k / 3 - 1) * 2;
        int xx = x + (k % 3 - 1) * 2;
        float zv = ((unsigned)yy < 96u && (unsigned)xx < 96u) ? zr[yy * 96 + xx] : 0.f;
        acc = fmaf(an[k * 9216 + p], zv, acc);
    }
    out[((long)n * 59 + o) * 9216 + p] = acc;
}

// ---------------------------------------------------------------------------
extern "C" void kernel_launch(void* const* d_in, const int* in_sizes, int n_in,
                              void* d_out, int out_size)
{
    (void)in_sizes; (void)n_in; (void)out_size;
    const float* c1    = (const float*)d_in[0];
    const float* c2    = (const float*)d_in[1];
    const float* x     = (const float*)d_in[2];
    const float* w_r1  = (const float*)d_in[3];
    const float* bnr1  = (const float*)d_in[4];
    const float* w_r2  = (const float*)d_in[5];
    const float* bnr2  = (const float*)d_in[6];
    const float* w_r3  = (const float*)d_in[7];
    const float* bnr3  = (const float*)d_in[8];
    const float* w_c5  = (const float*)d_in[17];
    const float* bnc5  = (const float*)d_in[18];
    const float* w_c6  = (const float*)d_in[19];
    const float* b_c6  = (const float*)d_in[20];

    float *r1p, *r2p, *t48p, *c2rp, *attp, *poolp, *ppolp, *pspp, *o5p, *z48p, *z96p;
    cudaGetSymbolAddress((void**)&r1p,  g_r1b);
    cudaGetSymbolAddress((void**)&r2p,  g_r2b);
    cudaGetSymbolAddress((void**)&t48p, g_t48);
    cudaGetSymbolAddress((void**)&c2rp, g_c2r);
    cudaGetSymbolAddress((void**)&attp, g_attb);
    cudaGetSymbolAddress((void**)&poolp, g_pool);
    cudaGetSymbolAddress((void**)&ppolp, g_ppol);
    cudaGetSymbolAddress((void**)&pspp, g_psp);
    cudaGetSymbolAddress((void**)&o5p,  g_out5);
    cudaGetSymbolAddress((void**)&z48p, g_z48);
    cudaGetSymbolAddress((void**)&z96p, g_z96);

    const int c5_smem = 3 * (ASZ + BSZ) * sizeof(float);  // 107520 B
    cudaFuncSetAttribute(c5_mma_kernel, cudaFuncAttributeMaxDynamicSharedMemorySize, c5_smem);

    // Launch order chosen so c5 is the 6th launch (ncu -s 5 -c 1 captures it).
    // --- pyramid pooling chain (1..3) ---
    pool_kernel<<<dim3(2048, 2), 64>>>(x, poolp);
    PoolWArgs pa;
    pa.w[0] = (const float*)d_in[9];  pa.bn[0] = (const float*)d_in[10];
    pa.w[1] = (const float*)d_in[11]; pa.bn[1] = (const float*)d_in[12];
    pa.w[2] = (const float*)d_in[13]; pa.bn[2] = (const float*)d_in[14];
    pa.w[3] = (const float*)d_in[15]; pa.bn[3] = (const float*)d_in[16];
    pooled_conv_kernel<<<6400, 256>>>(pa, poolp, ppolp);
    psp_assemble<<<73728, 256>>>(x, ppolp, pspp);

    // --- query branch (4..5) ---
    gemm_conv<64, 2, true, true, false, false><<<dim3(72, 1, 2), 128>>>(
        w_r1, c1, bnr1, r1p, 64, 2304, 96, 96, 9216, 256L * 9216, 64L * 9216);
    gemm_conv<64, 2, true, true, false, false><<<dim3(72, 1, 2), 128>>>(
        w_r2, r1p, bnr2, r2p, 64, 576, 96, 96, 9216, 64L * 9216, 64L * 9216);

    // --- conv5 on tensor cores (6) ---
    c5_mma_kernel<<<dim3(18, 4, 2), 256, c5_smem>>>(w_c5, pspp, bnc5, o5p);

    // --- key branch + attention (7..9) ---
    gemm_conv<64, 0, true, false, false, false><<<dim3(18, 1, 2), 128>>>(
        w_r3, c2, bnr3, t48p, 64, 512, 48, 48, 2304, 512L * 2304, 64L * 2304);
    ups48to96<true><<<4608, 256>>>(t48p, c2rp, 2 * 64 * 9216);
    att_kernel<<<dim3(36, 2), 256>>>(r2p, c2rp, attp);

    // --- conv6 pulled before upsample/aggregate (10..12) ---
    gemm_conv<64, 0, false, false, true, false><<<dim3(18, 1, 2), 128>>>(
        w_c6, o5p, nullptr, z48p, 59, 512, 48, 48, 2304, 512L * 2304, 59L * 2304);
    ups48to96<false><<<4248, 256>>>(z48p, z96p, 2 * 59 * 9216);
    final_kernel<<<dim3(36, 59, 2), 256>>>(attp, z96p, b_c6, (float*)d_out);
}

// round 9
// speedup vs baseline: 1.1769x; 1.1769x over previous
#include <cuda_runtime.h>
#include <cstdint>

// ---------------- scratch (device globals; no allocation allowed) ----------
__device__ float g_r1b [1179648];  // [2][64][96][96]
__device__ float g_r2b [1179648];  // [2][64][96][96]  query q
__device__ float g_t48 [294912];   // [2][64][48][48]
__device__ float g_c2r [1179648];  // [2][64][96][96]  keys
__device__ float g_attb[165888];   // [2][9][9216]
__device__ float g_pool[204800];
__device__ float g_ppol[51200];
__device__ float g_psp [18874368]; // [2][4096][48][48]
__device__ float g_out5[2359296];  // [2][512][48][48]
__device__ float g_z48 [271872];
__device__ float g_z96 [1087488];
__device__ float g_w5t [18874368]; // w_c5 transposed [36864][512]

__device__ __forceinline__ void mma16n8k8(float* c, const uint32_t* a, const uint32_t* b)
{
    asm volatile(
        "mma.sync.aligned.m16n8k8.row.col.f32.tf32.tf32.f32 "
        "{%0,%1,%2,%3}, {%4,%5,%6,%7}, {%8,%9}, {%0,%1,%2,%3};"
        : "+f"(c[0]), "+f"(c[1]), "+f"(c[2]), "+f"(c[3])
        : "r"(a[0]), "r"(a[1]), "r"(a[2]), "r"(a[3]), "r"(b[0]), "r"(b[1]));
}

// -------- weight transpose: dst[k][m] = src[m][k] --------------------------
__global__ void transpose_w(const float* __restrict__ src, float* __restrict__ dst,
                            int M, int K)
{
    __shared__ float tl[32][33];
    const int kb = blockIdx.x * 32, mb = blockIdx.y * 32;
    const int tx = threadIdx.x, ty0 = threadIdx.y;
    #pragma unroll
    for (int i = 0; i < 4; i++) {
        int ty = ty0 + i * 8;
        tl[ty][tx] = src[(long)(mb + ty) * K + kb + tx];
    }
    __syncthreads();
    #pragma unroll
    for (int i = 0; i < 4; i++) {
        int ty = ty0 + i * 8;
        dst[(long)(kb + ty) * M + mb + tx] = tl[tx][ty];
    }
}

// ===========================================================================
// conv5 via tf32 mma.sync, implicit im2col, 16 warps (warp tile 32x32).
//   CTA tile 128x128, KC=32, double-buffered smem (round-6 proven structure).
//   A (weights) pre-transposed to [K][M] -> float4 coalesced, conflict-free STS.
// ===========================================================================
#define KC   32
#define SA5  136
#define SB5  136
#define ASZ5 (KC * SA5)
#define BSZ5 (KC * SB5)

__global__ void __launch_bounds__(512, 1)
c5_mma_kernel(const float* __restrict__ At, const float* __restrict__ psp,
              const float* __restrict__ bnp, float* __restrict__ Out)
{
    extern __shared__ float sm[];
    float* As[2] = { sm, sm + ASZ5 };
    float* Bs[2] = { sm + 2 * ASZ5, sm + 2 * ASZ5 + BSZ5 };

    const int t    = threadIdx.x;
    const int wid  = t >> 5;
    const int lane = t & 31;
    const int gid  = lane >> 2;
    const int tig  = lane & 3;
    const int wm   = (wid & 3) * 32;    // 4 M-warps
    const int wn   = (wid >> 2) * 32;   // 4 N-warps

    const int img = blockIdx.z;
    const int bm  = blockIdx.y * 128;
    const int bp0 = blockIdx.x * 128;
    const float* Bn = psp + (long)img * 4096 * 2304;

    // A loader: 2 float4 per thread; idx = j*512 + t -> kk = idx>>5, mseg = idx&31
    int a_kk[2], a_ms[2];
    #pragma unroll
    for (int j = 0; j < 2; j++) { int idx = j * 512 + t; a_kk[j] = idx >> 5; a_ms[j] = idx & 31; }

    // B loader: 8 px per thread
    const int b_k  = t >> 4;            // 0..31
    const int b_n0 = (t & 15) * 8;
    const int pg0  = bp0 + b_n0;
    const int py0  = pg0 / 48;
    const int px0  = pg0 - py0 * 48;

    float4 arv[2];
    float  brv[8];

    auto fetchA = [&](int k0) {
        #pragma unroll
        for (int j = 0; j < 2; j++)
            arv[j] = *reinterpret_cast<const float4*>(At + (long)(k0 + a_kk[j]) * 512 + bm + a_ms[j] * 4);
    };
    auto fetchB = [&](int k0) {
        int k   = k0 + b_k;
        int cin = k / 9;
        int tap = k - cin * 9;
        int dy  = tap / 3 - 1;
        int dx  = tap - (tap / 3) * 3 - 1;
        int y   = py0 + dy;
        bool vy = (unsigned)y < 48u;
        int  xb = px0 + dx;
        const float* bp = Bn + (long)cin * 2304 + y * 48 + xb;
        #pragma unroll
        for (int j = 0; j < 8; j++) {
            int x = xb + j;
            brv[j] = (vy && (unsigned)x < 48u) ? __ldg(bp + j) : 0.f;
        }
    };
    auto stsA = [&](int buf) {
        #pragma unroll
        for (int j = 0; j < 2; j++)
            *reinterpret_cast<float4*>(As[buf] + a_kk[j] * SA5 + a_ms[j] * 4) = arv[j];
    };
    auto stsB = [&](int buf) {
        #pragma unroll
        for (int q = 0; q < 2; q++)
            *reinterpret_cast<float4*>(Bs[buf] + b_k * SB5 + b_n0 + q * 4) =
                make_float4(brv[q * 4], brv[q * 4 + 1], brv[q * 4 + 2], brv[q * 4 + 3]);
    };

    float acc[2][4][4];
    #pragma unroll
    for (int mt = 0; mt < 2; mt++)
        #pragma unroll
        for (int nt = 0; nt < 4; nt++)
            #pragma unroll
            for (int i = 0; i < 4; i++) acc[mt][nt][i] = 0.f;

    fetchA(0); fetchB(0);
    stsA(0); stsB(0);
    __syncthreads();

    const int NCH = 1152;
    int buf = 0;
    for (int it = 0; it < NCH; it++) {
        if (it + 1 < NCH) { fetchA((it + 1) * KC); fetchB((it + 1) * KC); }
        const float* A = As[buf];
        const float* B = Bs[buf];
        #pragma unroll
        for (int s = 0; s < 4; s++) {
            uint32_t af[2][4];
            uint32_t bf[4][2];
            #pragma unroll
            for (int mt = 0; mt < 2; mt++) {
                const float* ap = A + (s * 8 + tig) * SA5 + wm + mt * 16 + gid;
                af[mt][0] = __float_as_uint(ap[0]);
                af[mt][1] = __float_as_uint(ap[8]);
                af[mt][2] = __float_as_uint(ap[4 * SA5]);
                af[mt][3] = __float_as_uint(ap[4 * SA5 + 8]);
            }
            #pragma unroll
            for (int nt = 0; nt < 4; nt++) {
                const float* bp = B + (s * 8 + tig) * SB5 + wn + nt * 8 + gid;
                bf[nt][0] = __float_as_uint(bp[0]);
                bf[nt][1] = __float_as_uint(bp[4 * SB5]);
            }
            #pragma unroll
            for (int mt = 0; mt < 2; mt++)
                #pragma unroll
                for (int nt = 0; nt < 4; nt++)
                    mma16n8k8(acc[mt][nt], af[mt], bf[nt]);
        }
        if (it + 1 < NCH) { stsA(buf ^ 1); stsB(buf ^ 1); }
        __syncthreads();
        buf ^= 1;
    }

    #pragma unroll
    for (int mt = 0; mt < 2; mt++) {
        const int m0 = bm + wm + mt * 16 + gid;
        #pragma unroll
        for (int half = 0; half < 2; half++) {
            const int m = m0 + half * 8;
            const float g  = bnp[m], be = bnp[512 + m];
            const float mu = bnp[1024 + m], va = bnp[1536 + m];
            const float scale = g * rsqrtf(va + 1e-5f);
            const float shift = be - mu * scale;
            float* On = Out + ((long)img * 512 + m) * 2304 + bp0 + wn + tig * 2;
            #pragma unroll
            for (int nt = 0; nt < 4; nt++) {
                float2 v;
                v.x = fmaxf(fmaf(acc[mt][nt][half * 2],     scale, shift), 0.f);
                v.y = fmaxf(fmaf(acc[mt][nt][half * 2 + 1], scale, shift), 0.f);
                *reinterpret_cast<float2*>(On + nt * 8) = v;
            }
        }
    }
}

// ================= fp32 SGEMM (small convs) ================================
template<int TM, int DIL, bool BN, bool RELU, bool MCHECK, bool NCHECK>
__global__ void __launch_bounds__((TM/8)*16, 1)
gemm_conv(const float* __restrict__ A, const float* __restrict__ Bin,
          const float* __restrict__ bnp, float* __restrict__ Out,
          int M, int K, int H, int W, int Npix,
          long inStride, long outStride)
{
    constexpr int TN   = 128;
    constexpr int NT   = (TM / 8) * (TN / 8);
    constexpr int BVEC = (NT == 256) ? 4 : 8;

    __shared__ float As_[2][8][TM];
    __shared__ float Bs_[2][8][TN];

    const int tid = threadIdx.x;
    const int img = blockIdx.z;
    const float* Bn = Bin + (long)img * inStride;
    float*       On = Out + (long)img * outStride;
    const int bm  = blockIdx.y * TM;
    const int bp0 = blockIdx.x * TN;
    const int tr  = tid / 16;
    const int tc  = tid % 16;

    const int am = tid >> 1;
    const int ak = (tid & 1) * 4;
    const int bk = tid / (TN / BVEC);
    const int bp = (tid % (TN / BVEC)) * BVEC;

    float4 aReg;
    float  bReg[BVEC];

    auto fetch = [&](int k0) {
        int m = bm + am;
        if (!MCHECK || m < M)
            aReg = *reinterpret_cast<const float4*>(A + (long)m * K + k0 + ak);
        else
            aReg = make_float4(0.f, 0.f, 0.f, 0.f);
        int k = k0 + bk;
        if (DIL == 0) {
            const float* row = Bn + (long)k * Npix;
            if (!NCHECK) {
                #pragma unroll
                for (int j = 0; j < BVEC; j += 4) {
                    float4 v = *reinterpret_cast<const float4*>(row + bp0 + bp + j);
                    bReg[j] = v.x; bReg[j+1] = v.y; bReg[j+2] = v.z; bReg[j+3] = v.w;
                }
            } else {
                #pragma unroll
                for (int j = 0; j < BVEC; j++) {
                    int p = bp0 + bp + j;
                    bReg[j] = (p < Npix) ? row[p] : 0.f;
                }
            }
        } else {
            int cin = k / 9;
            int tap = k - cin * 9;
            int oy  = (tap / 3 - 1) * DIL;
            int ox  = (tap % 3 - 1) * DIL;
            const float* src = Bn + (long)cin * (H * W);
            #pragma unroll
            for (int j = 0; j < BVEC; j++) {
                int p  = bp0 + bp + j;
                int py = p / W;
                int px = p - py * W;
                int y  = py + oy;
                int x  = px + ox;
                bReg[j] = ((unsigned)y < (unsigned)H && (unsigned)x < (unsigned)W)
                          ? src[y * W + x] : 0.f;
            }
        }
    };
    auto put = [&](int buf) {
        As_[buf][ak + 0][am] = aReg.x;
        As_[buf][ak + 1][am] = aReg.y;
        As_[buf][ak + 2][am] = aReg.z;
        As_[buf][ak + 3][am] = aReg.w;
        #pragma unroll
        for (int j = 0; j < BVEC; j++) Bs_[buf][bk][bp + j] = bReg[j];
    };

    float acc[8][8];
    #pragma unroll
    for (int i = 0; i < 8; i++)
        #pragma unroll
        for (int j = 0; j < 8; j++) acc[i][j] = 0.f;

    fetch(0);
    put(0);
    __syncthreads();

    const int nK = K / 8;
    int buf = 0;
    for (int it = 0; it < nK; it++) {
        if (it + 1 < nK) fetch((it + 1) * 8);
        #pragma unroll
        for (int kk = 0; kk < 8; kk++) {
            float4 a0 = *reinterpret_cast<const float4*>(&As_[buf][kk][tr * 8]);
            float4 a1 = *reinterpret_cast<const float4*>(&As_[buf][kk][tr * 8 + 4]);
            float4 b0 = *reinterpret_cast<const float4*>(&Bs_[buf][kk][tc * 8]);
            float4 b1 = *reinterpret_cast<const float4*>(&Bs_[buf][kk][tc * 8 + 4]);
            float av[8] = {a0.x, a0.y, a0.z, a0.w, a1.x, a1.y, a1.z, a1.w};
            float bv[8] = {b0.x, b0.y, b0.z, b0.w, b1.x, b1.y, b1.z, b1.w};
            #pragma unroll
            for (int i = 0; i < 8; i++)
                #pragma unroll
                for (int j = 0; j < 8; j++)
                    acc[i][j] = fmaf(av[i], bv[j], acc[i][j]);
        }
        if (it + 1 < nK) put(buf ^ 1);
        __syncthreads();
        buf ^= 1;
    }

    #pragma unroll
    for (int i = 0; i < 8; i++) {
        int m = bm + tr * 8 + i;
        if (MCHECK && m >= M) continue;
        float scale = 1.f, shift = 0.f;
        if (BN) {
            float g  = bnp[m];
            float be = bnp[M + m];
            float mu = bnp[2 * M + m];
            float va = bnp[3 * M + m];
            scale = g * rsqrtf(va + 1e-5f);
            shift = be - mu * scale;
        }
        #pragma unroll
        for (int j = 0; j < 8; j++) {
            int p = bp0 + tc * 8 + j;
            if (NCHECK && p >= Npix) continue;
            float v = acc[i][j];
            if (BN)   v = fmaf(v, scale, shift);
            if (RELU) v = fmaxf(v, 0.f);
            On[(long)m * Npix + p] = v;
        }
    }
}

// -------- adaptive avg pool ------------------------------------------------
__global__ void pool_kernel(const float* __restrict__ x, float* __restrict__ pool)
{
    __shared__ float sm[2304];
    const int cin = blockIdx.x;
    const int n   = blockIdx.y;
    const float* src = x + ((long)n * 2048 + cin) * 2304;
    for (int i = threadIdx.x; i < 2304; i += blockDim.x) sm[i] = src[i];
    __syncthreads();
    int r = threadIdx.x;
    if (r < 50) {
        int sc, pi;
        if      (r < 1)  { sc = 0; pi = r; }
        else if (r < 5)  { sc = 1; pi = r - 1; }
        else if (r < 14) { sc = 2; pi = r - 5; }
        else             { sc = 3; pi = r - 14; }
        const int sides[4] = {1, 2, 3, 6};
        const int inoff[4] = {0, 2048, 10240, 28672};
        int side = sides[sc];
        int iy = pi / side, ix = pi % side;
        int bs = 48 / side;
        float s = 0.f;
        for (int yy = iy * bs; yy < (iy + 1) * bs; yy++)
            for (int xx = ix * bs; xx < (ix + 1) * bs; xx++)
                s += sm[yy * 48 + xx];
        pool[(long)n * 102400 + inoff[sc] + cin * (side * side) + pi] = s / (float)(bs * bs);
    }
}

struct PoolWArgs { const float* w[4]; const float* bn[4]; };

__global__ void pooled_conv_kernel(PoolWArgs args, const float* __restrict__ pool,
                                   float* __restrict__ ppool)
{
    int gw   = (blockIdx.x * blockDim.x + threadIdx.x) >> 5;
    int lane = threadIdx.x & 31;
    if (gw >= 51200) return;
    int n  = gw / 25600;
    int t  = gw % 25600;
    int pg = t / 512;
    int co = t % 512;
    int sc, pi;
    if      (pg < 1)  { sc = 0; pi = pg; }
    else if (pg < 5)  { sc = 1; pi = pg - 1; }
    else if (pg < 14) { sc = 2; pi = pg - 5; }
    else              { sc = 3; pi = pg - 14; }
    const int ssq[4]    = {1, 4, 9, 36};
    const int inoff[4]  = {0, 2048, 10240, 28672};
    const int outoff[4] = {0, 512, 2560, 7168};
    const float* w  = args.w[sc] + (long)co * 2048;
    const float* pb = pool + (long)n * 102400 + inoff[sc] + pi;
    int stride = ssq[sc];
    float acc = 0.f;
    for (int c = lane; c < 2048; c += 32)
        acc = fmaf(w[c], pb[(long)c * stride], acc);
    #pragma unroll
    for (int s = 16; s; s >>= 1) acc += __shfl_xor_sync(0xffffffffu, acc, s);
    if (lane == 0) {
        const float* bnp = args.bn[sc];
        float scale = bnp[co] * rsqrtf(bnp[1536 + co] + 1e-5f);
        float v = fmaf(acc, scale, bnp[512 + co] - bnp[1024 + co] * scale);
        ppool[(long)n * 25600 + outoff[sc] + co * stride + pi] = fmaxf(v, 0.f);
    }
}

__global__ void psp_assemble(const float* __restrict__ x, const float* __restrict__ ppool,
                             float* __restrict__ psp)
{
    long idx = (long)blockIdx.x * 256 + threadIdx.x;
    if (idx >= 18874368L) return;
    int p = (int)(idx % 2304);
    long t = idx / 2304;
    int c = (int)(t % 4096);
    int n = (int)(t / 4096);
    float v;
    if (c < 2048) {
        v = x[((long)n * 2048 + c) * 2304 + p];
    } else {
        int sc = (c - 2048) >> 9;
        int cc = (c - 2048) & 511;
        const int sides[4]  = {1, 2, 3, 6};
        const int outoff[4] = {0, 512, 2560, 7168};
        int s = sides[sc];
        const float* f = ppool + (long)n * 25600 + outoff[sc] + cc * s * s;
        if (s == 1) {
            v = f[0];
        } else {
            int y = p / 48, xx = p % 48;
            float ratio = (float)(s - 1) / 47.0f;
            float sy = y * ratio, sx = xx * ratio;
            int y0 = (int)sy, x0 = (int)sx;
            if (y0 > s - 1) y0 = s - 1;
            if (x0 > s - 1) x0 = s - 1;
            int y1 = min(y0 + 1, s - 1), x1 = min(x0 + 1, s - 1);
            float wy = sy - y0, wx = sx - x0;
            float r0 = f[y0 * s + x0] * (1.f - wx) + f[y0 * s + x1] * wx;
            float r1 = f[y1 * s + x0] * (1.f - wx) + f[y1 * s + x1] * wx;
            v = r0 * (1.f - wy) + r1 * wy;
        }
    }
    psp[idx] = v;
}

template<bool RELU>
__global__ void ups48to96(const float* __restrict__ in, float* __restrict__ out, int total)
{
    int idx = blockIdx.x * 256 + threadIdx.x;
    if (idx >= total) return;
    int p  = idx % 9216;
    int ch = idx / 9216;
    int y = p / 96, x = p % 96;
    const float r = 47.0f / 95.0f;
    float sy = y * r, sx = x * r;
    int y0 = (int)sy, x0 = (int)sx;
    if (y0 > 47) y0 = 47;
    if (x0 > 47) x0 = 47;
    int y1 = min(y0 + 1, 47), x1 = min(x0 + 1, 47);
    float wy = sy - y0, wx = sx - x0;
    const float* f = in + (long)ch * 2304;
    float v0 = f[y0 * 48 + x0] * (1.f - wx) + f[y0 * 48 + x1] * wx;
    float v1 = f[y1 * 48 + x0] * (1.f - wx) + f[y1 * 48 + x1] * wx;
    float v  = v0 * (1.f - wy) + v1 * wy;
    if (RELU) v = fmaxf(v, 0.f);
    out[idx] = v;
}

__global__ void att_kernel(const float* __restrict__ q, const float* __restrict__ kf,
                           float* __restrict__ att)
{
    int p = blockIdx.x * 256 + threadIdx.x;
    int n = blockIdx.y;
    if (p >= 9216) return;
    int y = p / 96, x = p % 96;
    int   offs[9];
    bool  valid[9];
    #pragma unroll
    for (int k = 0; k < 9; k++) {
        int yy = y + (k / 3 - 1) * 2;
        int xx = x + (k % 3 - 1) * 2;
        valid[k] = ((unsigned)yy < 96u) && ((unsigned)xx < 96u);
        offs[k]  = valid[k] ? yy * 96 + xx : 0;
    }
    float e[9];
    #pragma unroll
    for (int k = 0; k < 9; k++) e[k] = 0.f;
    const float* qn = q  + (long)n * 64 * 9216;
    const float* kn = kf + (long)n * 64 * 9216;
    for (int c = 0; c < 64; c++) {
        float qv = qn[c * 9216 + p];
        const float* base = kn + c * 9216;
        #pragma unroll
        for (int k = 0; k < 9; k++) {
            float kv = valid[k] ? base[offs[k]] : 0.f;
            e[k] = fmaf(qv, kv, e[k]);
        }
    }
    float mx = e[0];
    #pragma unroll
    for (int k = 1; k < 9; k++) mx = fmaxf(mx, e[k]);
    float sum = 0.f;
    #pragma unroll
    for (int k = 0; k < 9; k++) { e[k] = __expf(e[k] - mx); sum += e[k]; }
    float inv = 1.f / sum;
    #pragma unroll
    for (int k = 0; k < 9; k++)
        att[(long)n * 82944 + k * 9216 + p] = e[k] * inv;
}

__global__ void final_kernel(const float* __restrict__ att, const float* __restrict__ z,
                             const float* __restrict__ bias, float* __restrict__ out)
{
    int p = blockIdx.x * 256 + threadIdx.x;
    int o = blockIdx.y;
    int n = blockIdx.z;
    if (p >= 9216) return;
    int y = p / 96, x = p % 96;
    const float* zr = z   + ((long)n * 59 + o) * 9216;
    const float* an = att + (long)n * 82944;
    float acc = bias[o];
    #pragma unroll
    for (int k = 0; k < 9; k++) {
        int yy = y + (k / 3 - 1) * 2;
        int xx = x + (k % 3 - 1) * 2;
        float zv = ((unsigned)yy < 96u && (unsigned)xx < 96u) ? zr[yy * 96 + xx] : 0.f;
        acc = fmaf(an[k * 9216 + p], zv, acc);
    }
    out[((long)n * 59 + o) * 9216 + p] = acc;
}

// ---------------------------------------------------------------------------
extern "C" void kernel_launch(void* const* d_in, const int* in_sizes, int n_in,
                              void* d_out, int out_size)
{
    (void)in_sizes; (void)n_in; (void)out_size;
    const float* c1    = (const float*)d_in[0];
    const float* c2    = (const float*)d_in[1];
    const float* x     = (const float*)d_in[2];
    const float* w_r1  = (const float*)d_in[3];
    const float* bnr1  = (const float*)d_in[4];
    const float* w_r2  = (const float*)d_in[5];
    const float* bnr2  = (const float*)d_in[6];
    const float* w_r3  = (const float*)d_in[7];
    const float* bnr3  = (const float*)d_in[8];
    const float* w_c5  = (const float*)d_in[17];
    const float* bnc5  = (const float*)d_in[18];
    const float* w_c6  = (const float*)d_in[19];
    const float* b_c6  = (const float*)d_in[20];

    float *r1p, *r2p, *t48p, *c2rp, *attp, *poolp, *ppolp, *pspp, *o5p, *z48p, *z96p, *w5tp;
    cudaGetSymbolAddress((void**)&r1p,  g_r1b);
    cudaGetSymbolAddress((void**)&r2p,  g_r2b);
    cudaGetSymbolAddress((void**)&t48p, g_t48);
    cudaGetSymbolAddress((void**)&c2rp, g_c2r);
    cudaGetSymbolAddress((void**)&attp, g_attb);
    cudaGetSymbolAddress((void**)&poolp, g_pool);
    cudaGetSymbolAddress((void**)&ppolp, g_ppol);
    cudaGetSymbolAddress((void**)&pspp, g_psp);
    cudaGetSymbolAddress((void**)&o5p,  g_out5);
    cudaGetSymbolAddress((void**)&z48p, g_z48);
    cudaGetSymbolAddress((void**)&z96p, g_z96);
    cudaGetSymbolAddress((void**)&w5tp, g_w5t);

    const int c5_smem = 2 * (ASZ5 + BSZ5) * sizeof(float);  // 69632 B
    cudaFuncSetAttribute(c5_mma_kernel, cudaFuncAttributeMaxDynamicSharedMemorySize, c5_smem);

    // order chosen so c5_mma_kernel is the 6th launch (ncu -s 5 -c 1)
    // 1: weight transpose for c5
    transpose_w<<<dim3(1152, 16), dim3(32, 8)>>>(w_c5, w5tp, 512, 36864);
    // 2..4: pyramid pooling chain
    pool_kernel<<<dim3(2048, 2), 64>>>(x, poolp);
    PoolWArgs pa;
    pa.w[0] = (const float*)d_in[9];  pa.bn[0] = (const float*)d_in[10];
    pa.w[1] = (const float*)d_in[11]; pa.bn[1] = (const float*)d_in[12];
    pa.w[2] = (const float*)d_in[13]; pa.bn[2] = (const float*)d_in[14];
    pa.w[3] = (const float*)d_in[15]; pa.bn[3] = (const float*)d_in[16];
    pooled_conv_kernel<<<6400, 256>>>(pa, poolp, ppolp);
    psp_assemble<<<73728, 256>>>(x, ppolp, pspp);
    // 5: query conv1
    gemm_conv<64, 2, true, true, false, false><<<dim3(72, 1, 2), 128>>>(
        w_r1, c1, bnr1, r1p, 64, 2304, 96, 96, 9216, 256L * 9216, 64L * 9216);
    // 6: conv5 on tensor cores (profiled)
    c5_mma_kernel<<<dim3(18, 4, 2), 512, c5_smem>>>(w5tp, pspp, bnc5, o5p);
    // 7: query conv2
    gemm_conv<64, 2, true, true, false, false><<<dim3(72, 1, 2), 128>>>(
        w_r2, r1p, bnr2, r2p, 64, 576, 96, 96, 9216, 64L * 9216, 64L * 9216);
    // 8..10: key branch + attention
    gemm_conv<64, 0, true, false, false, false><<<dim3(18, 1, 2), 128>>>(
        w_r3, c2, bnr3, t48p, 64, 512, 48, 48, 2304, 512L * 2304, 64L * 2304);
    ups48to96<true><<<4608, 256>>>(t48p, c2rp, 2 * 64 * 9216);
    att_kernel<<<dim3(36, 2), 256>>>(r2p, c2rp, attp);
    // 11..13: conv6 (pre-upsample) + aggregate
    gemm_conv<64, 0, false, false, true, false><<<dim3(18, 1, 2), 128>>>(
        w_c6, o5p, nullptr, z48p, 59, 512, 48, 48, 2304, 512L * 2304, 59L * 2304);
    ups48to96<false><<<4248, 256>>>(z48p, z96p, 2 * 59 * 9216);
    final_kernel<<<dim3(36, 59, 2), 256>>>(attp, z96p, b_c6, (float*)d_out);
}

// round 10
// speedup vs baseline: 1.4600x; 1.2405x over previous
#include <cuda_runtime.h>
#include <cuda_fp16.h>
#include <cstdint>

// ---------------- scratch (device globals; no allocation allowed) ----------
__device__ float  g_r1b [1179648];  // [2][64][96][96]
__device__ float  g_r2b [1179648];  // [2][64][96][96]  query q
__device__ float  g_t48 [294912];   // [2][64][48][48]
__device__ float  g_c2r [1179648];  // [2][64][96][96]  keys
__device__ float  g_attb[165888];   // [2][9][9216]
__device__ float  g_pool[204800];
__device__ float  g_ppol[51200];
__device__ __half g_psph[18874368]; // [2][4096][48][48] psp features (half)
__device__ float  g_out5[2359296];  // [2][512][48][48]
__device__ float  g_z48 [271872];
__device__ float  g_z96 [1087488];
__device__ __half g_w5h [18874368]; // w_c5 as half, [512][36864]

// -------- convert w_c5 to half ---------------------------------------------
__global__ void w2h_kernel(const float* __restrict__ src, __half* __restrict__ dst)
{
    long i = ((long)blockIdx.x * 256 + threadIdx.x) * 4;
    if (i >= 18874368L) return;
    float4 v = *reinterpret_cast<const float4*>(src + i);
    dst[i]     = __float2half(v.x);
    dst[i + 1] = __float2half(v.y);
    dst[i + 2] = __float2half(v.z);
    dst[i + 3] = __float2half(v.w);
}

__device__ __forceinline__ void mma16n8k16(float* c, const uint32_t* a, const uint32_t* b)
{
    asm volatile(
        "mma.sync.aligned.m16n8k16.row.col.f32.f16.f16.f32 "
        "{%0,%1,%2,%3}, {%4,%5,%6,%7}, {%8,%9}, {%0,%1,%2,%3};"
        : "+f"(c[0]), "+f"(c[1]), "+f"(c[2]), "+f"(c[3])
        : "r"(a[0]), "r"(a[1]), "r"(a[2]), "r"(a[3]), "r"(b[0]), "r"(b[1]));
}

// ===========================================================================
// conv5 via fp16 mma.sync (fp32 accum), implicit im2col.
//   CTA tile 128x128, KC=32, 16 warps (warp 32x32), double-buffered smem.
//   A smem [m][SAH=40 halves] (k-contiguous half2 -> k16 A fragments)
//   B smem [kpair][SBW=132 half2] (k-pairs -> b0/b1 natural uint32)
// ===========================================================================
#define KC5  32
#define SAH  40
#define SBW  132

__global__ void __launch_bounds__(512, 1)
c5_mma_kernel(const __half* __restrict__ Ah, const __half* __restrict__ psph,
              const float* __restrict__ bnp, float* __restrict__ Out)
{
    __shared__ __half   Asm[2][128 * SAH];
    __shared__ uint32_t Bsm[2][16 * SBW];

    const int t    = threadIdx.x;
    const int wid  = t >> 5;
    const int lane = t & 31;
    const int gid  = lane >> 2;
    const int tig  = lane & 3;
    const int wm   = (wid & 3) * 32;
    const int wn   = (wid >> 2) * 32;

    const int img = blockIdx.z;
    const int bm  = blockIdx.y * 128;
    const int bp0 = blockIdx.x * 128;
    const __half* Bn = psph + (long)img * 4096 * 2304;

    // A loader: row = t>>2 (0..127), seg = t&3 (16B units of the 64B k-chunk row)
    const int a_row = t >> 2;
    const int a_seg = t & 3;
    const __half* Ag = Ah + (long)(bm + a_row) * 36864 + a_seg * 8;

    // B loader: b_k = t>>4 (0..31), 8 consecutive px
    const int b_k  = t >> 4;
    const int b_n0 = (t & 15) * 8;
    const int pg0  = bp0 + b_n0;
    const int py0  = pg0 / 48;
    const int px0  = pg0 - py0 * 48;

    uint4    arv;
    uint16_t brv[8];

    auto fetchA = [&](int k0) {
        arv = *reinterpret_cast<const uint4*>(Ag + k0);
    };
    auto fetchB = [&](int k0) {
        int k   = k0 + b_k;
        int cin = k / 9;
        int tap = k - cin * 9;
        int dy  = tap / 3 - 1;
        int dx  = tap - (tap / 3) * 3 - 1;
        int y   = py0 + dy;
        bool vy = (unsigned)y < 48u;
        int  xb = px0 + dx;
        const __half* bp = Bn + (long)cin * 2304 + y * 48 + xb;
        #pragma unroll
        for (int j = 0; j < 8; j++) {
            int x = xb + j;
            brv[j] = (vy && (unsigned)x < 48u)
                     ? __half_as_ushort(__ldg(bp + j)) : (uint16_t)0;
        }
    };
    auto stsA = [&](int buf) {
        *reinterpret_cast<uint4*>(&Asm[buf][a_row * SAH + a_seg * 8]) = arv;
    };
    auto stsB = [&](int buf) {
        char* base = reinterpret_cast<char*>(&Bsm[buf][0])
                   + (b_k >> 1) * (SBW * 4) + (b_k & 1) * 2;
        #pragma unroll
        for (int j = 0; j < 8; j++)
            *reinterpret_cast<uint16_t*>(base + (b_n0 + j) * 4) = brv[j];
    };

    float acc[2][4][4];
    #pragma unroll
    for (int mt = 0; mt < 2; mt++)
        #pragma unroll
        for (int nt = 0; nt < 4; nt++)
            #pragma unroll
            for (int i = 0; i < 4; i++) acc[mt][nt][i] = 0.f;

    fetchA(0); fetchB(0);
    stsA(0); stsB(0);
    __syncthreads();

    const int NCH = 1152;  // 36864 / 32
    int buf = 0;
    for (int it = 0; it < NCH; it++) {
        if (it + 1 < NCH) { fetchA((it + 1) * KC5); fetchB((it + 1) * KC5); }
        const __half*   A = Asm[buf];
        const uint32_t* B = Bsm[buf];
        #pragma unroll
        for (int s = 0; s < 2; s++) {       // two k16 steps per chunk
            uint32_t af[2][4];
            uint32_t bf[4][2];
            #pragma unroll
            for (int mt = 0; mt < 2; mt++) {
                const int m = wm + mt * 16 + gid;
                const uint32_t* ap0 =
                    reinterpret_cast<const uint32_t*>(A + m * SAH + s * 16 + tig * 2);
                const uint32_t* ap1 =
                    reinterpret_cast<const uint32_t*>(A + (m + 8) * SAH + s * 16 + tig * 2);
                af[mt][0] = ap0[0];
                af[mt][1] = ap1[0];
                af[mt][2] = ap0[4];
                af[mt][3] = ap1[4];
            }
            #pragma unroll
            for (int nt = 0; nt < 4; nt++) {
                const int n = wn + nt * 8 + gid;
                bf[nt][0] = B[(s * 8 + tig) * SBW + n];
                bf[nt][1] = B[(s * 8 + tig + 4) * SBW + n];
            }
            #pragma unroll
            for (int mt = 0; mt < 2; mt++)
                #pragma unroll
                for (int nt = 0; nt < 4; nt++)
                    mma16n8k16(acc[mt][nt], af[mt], bf[nt]);
        }
        if (it + 1 < NCH) { stsA(buf ^ 1); stsB(buf ^ 1); }
        __syncthreads();
        buf ^= 1;
    }

    #pragma unroll
    for (int mt = 0; mt < 2; mt++) {
        const int m0 = bm + wm + mt * 16 + gid;
        #pragma unroll
        for (int half = 0; half < 2; half++) {
            const int m = m0 + half * 8;
            const float g  = bnp[m], be = bnp[512 + m];
            const float mu = bnp[1024 + m], va = bnp[1536 + m];
            const float scale = g * rsqrtf(va + 1e-5f);
            const float shift = be - mu * scale;
            float* On = Out + ((long)img * 512 + m) * 2304 + bp0 + wn + tig * 2;
            #pragma unroll
            for (int nt = 0; nt < 4; nt++) {
                float2 v;
                v.x = fmaxf(fmaf(acc[mt][nt][half * 2],     scale, shift), 0.f);
                v.y = fmaxf(fmaf(acc[mt][nt][half * 2 + 1], scale, shift), 0.f);
                *reinterpret_cast<float2*>(On + nt * 8) = v;
            }
        }
    }
}

// ========== fp32 SGEMM, 256 threads, tile 64x128 (dilated 3x3, M=64) =======
template<int DIL>
__global__ void __launch_bounds__(256, 1)
gemm_conv64(const float* __restrict__ A, const float* __restrict__ Bin,
            const float* __restrict__ bnp, float* __restrict__ Out,
            int K, int H, int W, long inStride)
{
    __shared__ float As_[2][8][64];
    __shared__ float Bs_[2][8][128];

    const int t   = threadIdx.x;
    const int img = blockIdx.z;
    const int Npix = H * W;
    const float* Bn = Bin + (long)img * inStride;
    float*       On = Out + (long)img * 64L * Npix;
    const int bp0 = blockIdx.x * 128;
    const int tr  = t >> 4;         // 0..15 -> 4 m-rows each
    const int tc  = t & 15;         // 0..15 -> 8 n-cols each

    const int am  = t >> 2;         // 0..63
    const int ak2 = (t & 3) * 2;    // 0,2,4,6
    const int bk  = t >> 5;         // 0..7
    const int bp4 = (t & 31) * 4;

    float2 aReg;
    float  bReg[4];

    auto fetch = [&](int k0) {
        aReg = *reinterpret_cast<const float2*>(A + (long)am * K + k0 + ak2);
        int k   = k0 + bk;
        int cin = k / 9;
        int tap = k - cin * 9;
        int oy  = (tap / 3 - 1) * DIL;
        int ox  = (tap % 3 - 1) * DIL;
        const float* src = Bn + (long)cin * Npix;
        #pragma unroll
        for (int j = 0; j < 4; j++) {
            int p  = bp0 + bp4 + j;
            int py = p / W;
            int px = p - py * W;
            int y  = py + oy;
            int x  = px + ox;
            bReg[j] = ((unsigned)y < (unsigned)H && (unsigned)x < (unsigned)W)
                      ? src[y * W + x] : 0.f;
        }
    };
    auto put = [&](int buf) {
        As_[buf][ak2 + 0][am] = aReg.x;
        As_[buf][ak2 + 1][am] = aReg.y;
        #pragma unroll
        for (int j = 0; j < 4; j++) Bs_[buf][bk][bp4 + j] = bReg[j];
    };

    float acc[4][8];
    #pragma unroll
    for (int i = 0; i < 4; i++)
        #pragma unroll
        for (int j = 0; j < 8; j++) acc[i][j] = 0.f;

    fetch(0);
    put(0);
    __syncthreads();

    const int nK = K / 8;
    int buf = 0;
    for (int it = 0; it < nK; it++) {
        if (it + 1 < nK) fetch((it + 1) * 8);
        #pragma unroll
        for (int kk = 0; kk < 8; kk++) {
            float4 a0 = *reinterpret_cast<const float4*>(&As_[buf][kk][tr * 4]);
            float4 b0 = *reinterpret_cast<const float4*>(&Bs_[buf][kk][tc * 8]);
            float4 b1 = *reinterpret_cast<const float4*>(&Bs_[buf][kk][tc * 8 + 4]);
            float av[4] = {a0.x, a0.y, a0.z, a0.w};
            float bv[8] = {b0.x, b0.y, b0.z, b0.w, b1.x, b1.y, b1.z, b1.w};
            #pragma unroll
            for (int i = 0; i < 4; i++)
                #pragma unroll
                for (int j = 0; j < 8; j++)
                    acc[i][j] = fmaf(av[i], bv[j], acc[i][j]);
        }
        if (it + 1 < nK) put(buf ^ 1);
        __syncthreads();
        buf ^= 1;
    }

    #pragma unroll
    for (int i = 0; i < 4; i++) {
        int m = tr * 4 + i;
        float g  = bnp[m];
        float be = bnp[64 + m];
        float mu = bnp[128 + m];
        float va = bnp[192 + m];
        float scale = g * rsqrtf(va + 1e-5f);
        float shift = be - mu * scale;
        #pragma unroll
        for (int j = 0; j < 8; j++) {
            int p = bp0 + tc * 8 + j;
            float v = fmaxf(fmaf(acc[i][j], scale, shift), 0.f);
            On[(long)m * Npix + p] = v;
        }
    }
}

// ================= fp32 SGEMM (1x1 convs) — unchanged ======================
template<int TM, int DIL, bool BN, bool RELU, bool MCHECK, bool NCHECK>
__global__ void __launch_bounds__((TM/8)*16, 1)
gemm_conv(const float* __restrict__ A, const float* __restrict__ Bin,
          const float* __restrict__ bnp, float* __restrict__ Out,
          int M, int K, int H, int W, int Npix,
          long inStride, long outStride)
{
    constexpr int TN   = 128;
    constexpr int NT   = (TM / 8) * (TN / 8);
    constexpr int BVEC = (NT == 256) ? 4 : 8;

    __shared__ float As_[2][8][TM];
    __shared__ float Bs_[2][8][TN];

    const int tid = threadIdx.x;
    const int img = blockIdx.z;
    const float* Bn = Bin + (long)img * inStride;
    float*       On = Out + (long)img * outStride;
    const int bm  = blockIdx.y * TM;
    const int bp0 = blockIdx.x * TN;
    const int tr  = tid / 16;
    const int tc  = tid % 16;

    const int am = tid >> 1;
    const int ak = (tid & 1) * 4;
    const int bk = tid / (TN / BVEC);
    const int bp = (tid % (TN / BVEC)) * BVEC;

    float4 aReg;
    float  bReg[BVEC];

    auto fetch = [&](int k0) {
        int m = bm + am;
        if (!MCHECK || m < M)
            aReg = *reinterpret_cast<const float4*>(A + (long)m * K + k0 + ak);
        else
            aReg = make_float4(0.f, 0.f, 0.f, 0.f);
        int k = k0 + bk;
        if (DIL == 0) {
            const float* row = Bn + (long)k * Npix;
            if (!NCHECK) {
                #pragma unroll
                for (int j = 0; j < BVEC; j += 4) {
                    float4 v = *reinterpret_cast<const float4*>(row + bp0 + bp + j);
                    bReg[j] = v.x; bReg[j+1] = v.y; bReg[j+2] = v.z; bReg[j+3] = v.w;
                }
            } else {
                #pragma unroll
                for (int j = 0; j < BVEC; j++) {
                    int p = bp0 + bp + j;
                    bReg[j] = (p < Npix) ? row[p] : 0.f;
                }
            }
        } else {
            int cin = k / 9;
            int tap = k - cin * 9;
            int oy  = (tap / 3 - 1) * DIL;
            int ox  = (tap % 3 - 1) * DIL;
            const float* src = Bn + (long)cin * (H * W);
            #pragma unroll
            for (int j = 0; j < BVEC; j++) {
                int p  = bp0 + bp + j;
                int py = p / W;
                int px = p - py * W;
                int y  = py + oy;
                int x  = px + ox;
                bReg[j] = ((unsigned)y < (unsigned)H && (unsigned)x < (unsigned)W)
                          ? src[y * W + x] : 0.f;
            }
        }
    };
    auto put = [&](int buf) {
        As_[buf][ak + 0][am] = aReg.x;
        As_[buf][ak + 1][am] = aReg.y;
        As_[buf][ak + 2][am] = aReg.z;
        As_[buf][ak + 3][am] = aReg.w;
        #pragma unroll
        for (int j = 0; j < BVEC; j++) Bs_[buf][bk][bp + j] = bReg[j];
    };

    float acc[8][8];
    #pragma unroll
    for (int i = 0; i < 8; i++)
        #pragma unroll
        for (int j = 0; j < 8; j++) acc[i][j] = 0.f;

    fetch(0);
    put(0);
    __syncthreads();

    const int nK = K / 8;
    int buf = 0;
    for (int it = 0; it < nK; it++) {
        if (it + 1 < nK) fetch((it + 1) * 8);
        #pragma unroll
        for (int kk = 0; kk < 8; kk++) {
            float4 a0 = *reinterpret_cast<const float4*>(&As_[buf][kk][tr * 8]);
            float4 a1 = *reinterpret_cast<const float4*>(&As_[buf][kk][tr * 8 + 4]);
            float4 b0 = *reinterpret_cast<const float4*>(&Bs_[buf][kk][tc * 8]);
            float4 b1 = *reinterpret_cast<const float4*>(&Bs_[buf][kk][tc * 8 + 4]);
            float av[8] = {a0.x, a0.y, a0.z, a0.w, a1.x, a1.y, a1.z, a1.w};
            float bv[8] = {b0.x, b0.y, b0.z, b0.w, b1.x, b1.y, b1.z, b1.w};
            #pragma unroll
            for (int i = 0; i < 8; i++)
                #pragma unroll
                for (int j = 0; j < 8; j++)
                    acc[i][j] = fmaf(av[i], bv[j], acc[i][j]);
        }
        if (it + 1 < nK) put(buf ^ 1);
        __syncthreads();
        buf ^= 1;
    }

    #pragma unroll
    for (int i = 0; i < 8; i++) {
        int m = bm + tr * 8 + i;
        if (MCHECK && m >= M) continue;
        float scale = 1.f, shift = 0.f;
        if (BN) {
            float g  = bnp[m];
            float be = bnp[M + m];
            float mu = bnp[2 * M + m];
            float va = bnp[3 * M + m];
            scale = g * rsqrtf(va + 1e-5f);
            shift = be - mu * scale;
        }
        #pragma unroll
        for (int j = 0; j < 8; j++) {
            int p = bp0 + tc * 8 + j;
            if (NCHECK && p >= Npix) continue;
            float v = acc[i][j];
            if (BN)   v = fmaf(v, scale, shift);
            if (RELU) v = fmaxf(v, 0.f);
            On[(long)m * Npix + p] = v;
        }
    }
}

// -------- adaptive avg pool ------------------------------------------------
__global__ void pool_kernel(const float* __restrict__ x, float* __restrict__ pool)
{
    __shared__ float sm[2304];
    const int cin = blockIdx.x;
    const int n   = blockIdx.y;
    const float* src = x + ((long)n * 2048 + cin) * 2304;
    for (int i = threadIdx.x; i < 2304; i += blockDim.x) sm[i] = src[i];
    __syncthreads();
    int r = threadIdx.x;
    if (r < 50) {
        int sc, pi;
        if      (r < 1)  { sc = 0; pi = r; }
        else if (r < 5)  { sc = 1; pi = r - 1; }
        else if (r < 14) { sc = 2; pi = r - 5; }
        else             { sc = 3; pi = r - 14; }
        const int sides[4] = {1, 2, 3, 6};
        const int inoff[4] = {0, 2048, 10240, 28672};
        int side = sides[sc];
        int iy = pi / side, ix = pi % side;
        int bs = 48 / side;
        float s = 0.f;
        for (int yy = iy * bs; yy < (iy + 1) * bs; yy++)
            for (int xx = ix * bs; xx < (ix + 1) * bs; xx++)
                s += sm[yy * 48 + xx];
        pool[(long)n * 102400 + inoff[sc] + cin * (side * side) + pi] = s / (float)(bs * bs);
    }
}

struct PoolWArgs { const float* w[4]; const float* bn[4]; };

__global__ void pooled_conv_kernel(PoolWArgs args, const float* __restrict__ pool,
                                   float* __restrict__ ppool)
{
    int gw   = (blockIdx.x * blockDim.x + threadIdx.x) >> 5;
    int lane = threadIdx.x & 31;
    if (gw >= 51200) return;
    int n  = gw / 25600;
    int t  = gw % 25600;
    int pg = t / 512;
    int co = t % 512;
    int sc, pi;
    if      (pg < 1)  { sc = 0; pi = pg; }
    else if (pg < 5)  { sc = 1; pi = pg - 1; }
    else if (pg < 14) { sc = 2; pi = pg - 5; }
    else              { sc = 3; pi = pg - 14; }
    const int ssq[4]    = {1, 4, 9, 36};
    const int inoff[4]  = {0, 2048, 10240, 28672};
    const int outoff[4] = {0, 512, 2560, 7168};
    const float* w  = args.w[sc] + (long)co * 2048;
    const float* pb = pool + (long)n * 102400 + inoff[sc] + pi;
    int stride = ssq[sc];
    float acc = 0.f;
    for (int c = lane; c < 2048; c += 32)
        acc = fmaf(w[c], pb[(long)c * stride], acc);
    #pragma unroll
    for (int s = 16; s; s >>= 1) acc += __shfl_xor_sync(0xffffffffu, acc, s);
    if (lane == 0) {
        const float* bnp = args.bn[sc];
        float scale = bnp[co] * rsqrtf(bnp[1536 + co] + 1e-5f);
        float v = fmaf(acc, scale, bnp[512 + co] - bnp[1024 + co] * scale);
        ppool[(long)n * 25600 + outoff[sc] + co * stride + pi] = fmaxf(v, 0.f);
    }
}

// -------- assemble psp (writes HALF for the fp16 GEMM) ---------------------
__global__ void psp_assemble(const float* __restrict__ x, const float* __restrict__ ppool,
                             __half* __restrict__ psp)
{
    long idx = (long)blockIdx.x * 256 + threadIdx.x;
    if (idx >= 18874368L) return;
    int p = (int)(idx % 2304);
    long t = idx / 2304;
    int c = (int)(t % 4096);
    int n = (int)(t / 4096);
    float v;
    if (c < 2048) {
        v = x[((long)n * 2048 + c) * 2304 + p];
    } else {
        int sc = (c - 2048) >> 9;
        int cc = (c - 2048) & 511;
        const int sides[4]  = {1, 2, 3, 6};
        const int outoff[4] = {0, 512, 2560, 7168};
        int s = sides[sc];
        const float* f = ppool + (long)n * 25600 + outoff[sc] + cc * s * s;
        if (s == 1) {
            v = f[0];
        } else {
            int y = p / 48, xx = p % 48;
            float ratio = (float)(s - 1) / 47.0f;
            float sy = y * ratio, sx = xx * ratio;
            int y0 = (int)sy, x0 = (int)sx;
            if (y0 > s - 1) y0 = s - 1;
            if (x0 > s - 1) x0 = s - 1;
            int y1 = min(y0 + 1, s - 1), x1 = min(x0 + 1, s - 1);
            float wy = sy - y0, wx = sx - x0;
            float r0 = f[y0 * s + x0] * (1.f - wx) + f[y0 * s + x1] * wx;
            float r1 = f[y1 * s + x0] * (1.f - wx) + f[y1 * s + x1] * wx;
            v = r0 * (1.f - wy) + r1 * wy;
        }
    }
    psp[idx] = __float2half(v);
}

template<bool RELU>
__global__ void ups48to96(const float* __restrict__ in, float* __restrict__ out, int total)
{
    int idx = blockIdx.x * 256 + threadIdx.x;
    if (idx >= total) return;
    int p  = idx % 9216;
    int ch = idx / 9216;
    int y = p / 96, x = p % 96;
    const float r = 47.0f / 95.0f;
    float sy = y * r, sx = x * r;
    int y0 = (int)sy, x0 = (int)sx;
    if (y0 > 47) y0 = 47;
    if (x0 > 47) x0 = 47;
    int y1 = min(y0 + 1, 47), x1 = min(x0 + 1, 47);
    float wy = sy - y0, wx = sx - x0;
    const float* f = in + (long)ch * 2304;
    float v0 = f[y0 * 48 + x0] * (1.f - wx) + f[y0 * 48 + x1] * wx;
    float v1 = f[y1 * 48 + x0] * (1.f - wx) + f[y1 * 48 + x1] * wx;
    float v  = v0 * (1.f - wy) + v1 * wy;
    if (RELU) v = fmaxf(v, 0.f);
    out[idx] = v;
}

__global__ void att_kernel(const float* __restrict__ q, const float* __restrict__ kf,
                           float* __restrict__ att)
{
    int p = blockIdx.x * 256 + threadIdx.x;
    int n = blockIdx.y;
    if (p >= 9216) return;
    int y = p / 96, x = p % 96;
    int   offs[9];
    bool  valid[9];
    #pragma unroll
    for (int k = 0; k < 9; k++) {
        int yy = y + (k / 3 - 1) * 2;
        int xx = x + (k % 3 - 1) * 2;
        valid[k] = ((unsigned)yy < 96u) && ((unsigned)xx < 96u);
        offs[k]  = valid[k] ? yy * 96 + xx : 0;
    }
    float e[9];
    #pragma unroll
    for (int k = 0; k < 9; k++) e[k] = 0.f;
    const float* qn = q  + (long)n * 64 * 9216;
    const float* kn = kf + (long)n * 64 * 9216;
    for (int c = 0; c < 64; c++) {
        float qv = qn[c * 9216 + p];
        const float* base = kn + c * 9216;
        #pragma unroll
        for (int k = 0; k < 9; k++) {
            float kv = valid[k] ? base[offs[k]] : 0.f;
            e[k] = fmaf(qv, kv, e[k]);
        }
    }
    float mx = e[0];
    #pragma unroll
    for (int k = 1; k < 9; k++) mx = fmaxf(mx, e[k]);
    float sum = 0.f;
    #pragma unroll
    for (int k = 0; k < 9; k++) { e[k] = __expf(e[k] - mx); sum += e[k]; }
    float inv = 1.f / sum;
    #pragma unroll
    for (int k = 0; k < 9; k++)
        att[(long)n * 82944 + k * 9216 + p] = e[k] * inv;
}

__global__ void final_kernel(const float* __restrict__ att, const float* __restrict__ z,
                             const float* __restrict__ bias, float* __restrict__ out)
{
    int p = blockIdx.x * 256 + threadIdx.x;
    int o = blockIdx.y;
    int n = blockIdx.z;
    if (p >= 9216) return;
    int y = p / 96, x = p % 96;
    const float* zr = z   + ((long)n * 59 + o) * 9216;
    const float* an = att + (long)n * 82944;
    float acc = bias[o];
    #pragma unroll
    for (int k = 0; k < 9; k++) {
        int yy = y + (k / 3 - 1) * 2;
        int xx = x + (k % 3 - 1) * 2;
        float zv = ((unsigned)yy < 96u && (unsigned)xx < 96u) ? zr[yy * 96 + xx] : 0.f;
        acc = fmaf(an[k * 9216 + p], zv, acc);
    }
    out[((long)n * 59 + o) * 9216 + p] = acc;
}

// ---------------------------------------------------------------------------
extern "C" void kernel_launch(void* const* d_in, const int* in_sizes, int n_in,
                              void* d_out, int out_size)
{
    (void)in_sizes; (void)n_in; (void)out_size;
    const float* c1    = (const float*)d_in[0];
    const float* c2    = (const float*)d_in[1];
    const float* x     = (const float*)d_in[2];
    const float* w_r1  = (const float*)d_in[3];
    const float* bnr1  = (const float*)d_in[4];
    const float* w_r2  = (const float*)d_in[5];
    const float* bnr2  = (const float*)d_in[6];
    const float* w_r3  = (const float*)d_in[7];
    const float* bnr3  = (const float*)d_in[8];
    const float* w_c5  = (const float*)d_in[17];
    const float* bnc5  = (const float*)d_in[18];
    const float* w_c6  = (const float*)d_in[19];
    const float* b_c6  = (const float*)d_in[20];

    float *r1p, *r2p, *t48p, *c2rp, *attp, *poolp, *ppolp, *o5p, *z48p, *z96p;
    __half *psphp, *w5hp;
    cudaGetSymbolAddress((void**)&r1p,  g_r1b);
    cudaGetSymbolAddress((void**)&r2p,  g_r2b);
    cudaGetSymbolAddress((void**)&t48p, g_t48);
    cudaGetSymbolAddress((void**)&c2rp, g_c2r);
    cudaGetSymbolAddress((void**)&attp, g_attb);
    cudaGetSymbolAddress((void**)&poolp, g_pool);
    cudaGetSymbolAddress((void**)&ppolp, g_ppol);
    cudaGetSymbolAddress((void**)&psphp, g_psph);
    cudaGetSymbolAddress((void**)&o5p,  g_out5);
    cudaGetSymbolAddress((void**)&z48p, g_z48);
    cudaGetSymbolAddress((void**)&z96p, g_z96);
    cudaGetSymbolAddress((void**)&w5hp, g_w5h);

    // 1: convert c5 weights to half
    w2h_kernel<<<18432, 256>>>(w_c5, w5hp);
    // 2..4: pyramid pooling chain -> psp (half)
    pool_kernel<<<dim3(2048, 2), 64>>>(x, poolp);
    PoolWArgs pa;
    pa.w[0] = (const float*)d_in[9];  pa.bn[0] = (const float*)d_in[10];
    pa.w[1] = (const float*)d_in[11]; pa.bn[1] = (const float*)d_in[12];
    pa.w[2] = (const float*)d_in[13]; pa.bn[2] = (const float*)d_in[14];
    pa.w[3] = (const float*)d_in[15]; pa.bn[3] = (const float*)d_in[16];
    pooled_conv_kernel<<<6400, 256>>>(pa, poolp, ppolp);
    psp_assemble<<<73728, 256>>>(x, ppolp, psphp);
    // 5: query conv1 (256-thread fp32)
    gemm_conv64<2><<<dim3(72, 1, 2), 256>>>(w_r1, c1, bnr1, r1p, 2304, 96, 96, 256L * 9216);
    // 6: conv5 on tensor cores (fp16 inputs, fp32 accum)
    c5_mma_kernel<<<dim3(18, 4, 2), 512>>>(w5hp, psphp, bnc5, o5p);
    // 7: query conv2
    gemm_conv64<2><<<dim3(72, 1, 2), 256>>>(w_r2, r1p, bnr2, r2p, 576, 96, 96, 64L * 9216);
    // 8..10: key branch + attention
    gemm_conv<64, 0, true, false, false, false><<<dim3(18, 1, 2), 128>>>(
        w_r3, c2, bnr3, t48p, 64, 512, 48, 48, 2304, 512L * 2304, 64L * 2304);
    ups48to96<true><<<4608, 256>>>(t48p, c2rp, 2 * 64 * 9216);
    att_kernel<<<dim3(36, 2), 256>>>(r2p, c2rp, attp);
    // 11..13: conv6 (pre-upsample) + aggregate
    gemm_conv<64, 0, false, false, true, false><<<dim3(18, 1, 2), 128>>>(
        w_c6, o5p, nullptr, z48p, 59, 512, 48, 48, 2304, 512L * 2304, 59L * 2304);
    ups48to96<false><<<4248, 256>>>(z48p, z96p, 2 * 59 * 9216);
    final_kernel<<<dim3(36, 59, 2), 256>>>(attp, z96p, b_c6, (float*)d_out);
}

// round 11
// speedup vs baseline: 1.7649x; 1.2089x over previous
#include <cuda_runtime.h>
#include <cuda_fp16.h>
#include <cstdint>

// ---------------- scratch (device globals; no allocation allowed) ----------
__device__ float  g_r1b [1179648];  // [2][64][96][96]
__device__ float  g_r2b [1179648];  // [2][64][96][96]  query q
__device__ float  g_t48 [294912];   // [2][64][48][48]
__device__ float  g_c2r [1179648];  // [2][64][96][96]  keys
__device__ float  g_attb[165888];   // [2][9][9216]
__device__ float  g_pool[204800];
__device__ float  g_ppol[51200];
__device__ __half g_psph[18874368]; // [2][4096][48][48] psp features (half)
__device__ float  g_out5[2359296];  // [2][512][48][48]
__device__ float  g_z48 [271872];
__device__ float  g_z96 [1087488];
__device__ __half g_w5h [18874368]; // w_c5 as half, [512][36864]

__device__ __forceinline__ uint32_t smem_u32(const void* p) {
    uint32_t a;
    asm("{ .reg .u64 t; cvta.to.shared.u64 t, %1; cvt.u32.u64 %0, t; }" : "=r"(a) : "l"(p));
    return a;
}
__device__ __forceinline__ void ldsm_x4(uint32_t& r0, uint32_t& r1, uint32_t& r2,
                                        uint32_t& r3, uint32_t addr) {
    asm volatile("ldmatrix.sync.aligned.m8n8.x4.shared.b16 {%0,%1,%2,%3}, [%4];"
                 : "=r"(r0), "=r"(r1), "=r"(r2), "=r"(r3) : "r"(addr));
}
__device__ __forceinline__ void mma16n8k16(float* c, const uint32_t* a, const uint32_t* b)
{
    asm volatile(
        "mma.sync.aligned.m16n8k16.row.col.f32.f16.f16.f32 "
        "{%0,%1,%2,%3}, {%4,%5,%6,%7}, {%8,%9}, {%0,%1,%2,%3};"
        : "+f"(c[0]), "+f"(c[1]), "+f"(c[2]), "+f"(c[3])
        : "r"(a[0]), "r"(a[1]), "r"(a[2]), "r"(a[3]), "r"(b[0]), "r"(b[1]));
}

// -------- convert w_c5 to half ---------------------------------------------
__global__ void w2h_kernel(const float* __restrict__ src, __half* __restrict__ dst)
{
    long i = ((long)blockIdx.x * 256 + threadIdx.x) * 4;
    if (i >= 18874368L) return;
    float4 v = *reinterpret_cast<const float4*>(src + i);
    dst[i]     = __float2half(v.x);
    dst[i + 1] = __float2half(v.y);
    dst[i + 2] = __float2half(v.z);
    dst[i + 3] = __float2half(v.w);
}

// ===========================================================================
// conv5: fp16 mma.sync + ldmatrix, implicit im2col.
//   CTA 128x128, KC=64, 16 warps (warp 32x32), double-buffered dynamic smem.
//   A smem [m][72h] (row-major k), B smem [n][72h] (n-major = B^T) —
//   stride 72h = 144B -> LDSM rows hit distinct banks; 16B-aligned rows.
// ===========================================================================
#define KC5  64
#define SAK  72
#define HBUF (2 * 128 * SAK)   // halves per (A|B) pair

__global__ void __launch_bounds__(512, 1)
c5_mma_kernel(const __half* __restrict__ Ah, const __half* __restrict__ psph,
              const float* __restrict__ bnp, float* __restrict__ Out)
{
    extern __shared__ __half smh[];
    const uint32_t smbase = smem_u32(smh);

    const int t    = threadIdx.x;
    const int wid  = t >> 5;
    const int lane = t & 31;
    const int gid  = lane >> 2;
    const int tig  = lane & 3;
    const int wm   = (wid & 3) * 32;
    const int wn   = (wid >> 2) * 32;

    const int img = blockIdx.z;
    const int bm  = blockIdx.y * 128;
    const int bp0 = blockIdx.x * 128;
    const __half* Bn = psph + (long)img * 4096 * 2304;

    // ldmatrix lane geometry
    const int rowA = lane & 15;
    const int colA = (lane & 16) ? 8 : 0;
    const int rowB = (lane & 7) + ((lane & 16) ? 8 : 0);
    const int colB = (lane & 8) ? 8 : 0;

    // A loader: 2 units of 16B; unit u = j*512+t -> m = (u>>3)&127? (64 m per j)
    const int a_m   = t >> 3;          // 0..63
    const int a_seg = t & 7;           // 16B segment in 64-k row

    // B loader: 2 units; unit u = j*512+t -> n = u&127, kgroup = u>>7 (0..7)
    int b_n[2], b_kg[2], b_py[2], b_px[2];
    #pragma unroll
    for (int u = 0; u < 2; u++) {
        int unit = u * 512 + t;
        b_n[u]  = unit & 127;
        b_kg[u] = unit >> 7;
        int pg  = bp0 + b_n[u];
        b_py[u] = pg / 48;
        b_px[u] = pg - b_py[u] * 48;
    }

    uint4 arv[2];
    __align__(16) uint16_t brv[2][8];

    auto fetchA = [&](int k0) {
        #pragma unroll
        for (int j = 0; j < 2; j++)
            arv[j] = *reinterpret_cast<const uint4*>(
                Ah + (long)(bm + a_m + j * 64) * 36864 + k0 + a_seg * 8);
    };
    auto fetchB = [&](int k0) {
        #pragma unroll
        for (int u = 0; u < 2; u++) {
            #pragma unroll
            for (int j = 0; j < 8; j++) {
                int k   = k0 + b_kg[u] * 8 + j;
                int cin = k / 9;
                int tap = k - cin * 9;
                int dy  = tap / 3 - 1;
                int dx  = tap - (tap / 3) * 3 - 1;
                int y   = b_py[u] + dy;
                int x   = b_px[u] + dx;
                brv[u][j] = ((unsigned)y < 48u && (unsigned)x < 48u)
                            ? __half_as_ushort(__ldg(Bn + (long)cin * 2304 + y * 48 + x))
                            : (uint16_t)0;
            }
        }
    };
    auto stsAB = [&](int buf) {
        __half* A = smh + buf * HBUF;
        __half* B = A + 128 * SAK;
        #pragma unroll
        for (int j = 0; j < 2; j++)
            *reinterpret_cast<uint4*>(A + (a_m + j * 64) * SAK + a_seg * 8) = arv[j];
        #pragma unroll
        for (int u = 0; u < 2; u++)
            *reinterpret_cast<uint4*>(B + b_n[u] * SAK + b_kg[u] * 8) =
                *reinterpret_cast<const uint4*>(brv[u]);
    };

    float acc[2][4][4];
    #pragma unroll
    for (int mt = 0; mt < 2; mt++)
        #pragma unroll
        for (int nt = 0; nt < 4; nt++)
            #pragma unroll
            for (int i = 0; i < 4; i++) acc[mt][nt][i] = 0.f;

    fetchA(0); fetchB(0);
    stsAB(0);
    __syncthreads();

    const int NCH = 576;  // 36864 / 64
    int buf = 0;
    for (int it = 0; it < NCH; it++) {
        if (it + 1 < NCH) { fetchA((it + 1) * KC5); fetchB((it + 1) * KC5); }
        const uint32_t Abase = smbase + (uint32_t)buf * (HBUF * 2);
        const uint32_t Bbase = Abase + 128 * SAK * 2;
        #pragma unroll
        for (int s = 0; s < 4; s++) {
            uint32_t af[2][4];
            uint32_t bf[4][2];
            #pragma unroll
            for (int mt = 0; mt < 2; mt++)
                ldsm_x4(af[mt][0], af[mt][1], af[mt][2], af[mt][3],
                        Abase + (uint32_t)((wm + mt * 16 + rowA) * SAK
                                           + s * 16 + colA) * 2u);
            #pragma unroll
            for (int np = 0; np < 2; np++)
                ldsm_x4(bf[2 * np][0], bf[2 * np][1], bf[2 * np + 1][0], bf[2 * np + 1][1],
                        Bbase + (uint32_t)((wn + np * 16 + rowB) * SAK
                                           + s * 16 + colB) * 2u);
            #pragma unroll
            for (int mt = 0; mt < 2; mt++)
                #pragma unroll
                for (int nt = 0; nt < 4; nt++)
                    mma16n8k16(acc[mt][nt], af[mt], bf[nt]);
        }
        if (it + 1 < NCH) stsAB(buf ^ 1);
        __syncthreads();
        buf ^= 1;
    }

    #pragma unroll
    for (int mt = 0; mt < 2; mt++) {
        const int m0 = bm + wm + mt * 16 + gid;
        #pragma unroll
        for (int half = 0; half < 2; half++) {
            const int m = m0 + half * 8;
            const float g  = bnp[m], be = bnp[512 + m];
            const float mu = bnp[1024 + m], va = bnp[1536 + m];
            const float scale = g * rsqrtf(va + 1e-5f);
            const float shift = be - mu * scale;
            float* On = Out + ((long)img * 512 + m) * 2304 + bp0 + wn + tig * 2;
            #pragma unroll
            for (int nt = 0; nt < 4; nt++) {
                float2 v;
                v.x = fmaxf(fmaf(acc[mt][nt][half * 2],     scale, shift), 0.f);
                v.y = fmaxf(fmaf(acc[mt][nt][half * 2 + 1], scale, shift), 0.f);
                *reinterpret_cast<float2*>(On + nt * 8) = v;
            }
        }
    }
}

// ========== fp32 SGEMM, 256 threads, tile 64x128 (dilated 3x3, M=64) =======
template<int DIL>
__global__ void __launch_bounds__(256, 1)
gemm_conv64(const float* __restrict__ A, const float* __restrict__ Bin,
            const float* __restrict__ bnp, float* __restrict__ Out,
            int K, int H, int W, long inStride)
{
    __shared__ float As_[2][8][64];
    __shared__ float Bs_[2][8][128];

    const int t   = threadIdx.x;
    const int img = blockIdx.z;
    const int Npix = H * W;
    const float* Bn = Bin + (long)img * inStride;
    float*       On = Out + (long)img * 64L * Npix;
    const int bp0 = blockIdx.x * 128;
    const int tr  = t >> 4;
    const int tc  = t & 15;

    const int am  = t >> 2;
    const int ak2 = (t & 3) * 2;
    const int bk  = t >> 5;
    const int bp4 = (t & 31) * 4;

    float2 aReg;
    float  bReg[4];

    auto fetch = [&](int k0) {
        aReg = *reinterpret_cast<const float2*>(A + (long)am * K + k0 + ak2);
        int k   = k0 + bk;
        int cin = k / 9;
        int tap = k - cin * 9;
        int oy  = (tap / 3 - 1) * DIL;
        int ox  = (tap % 3 - 1) * DIL;
        const float* src = Bn + (long)cin * Npix;
        #pragma unroll
        for (int j = 0; j < 4; j++) {
            int p  = bp0 + bp4 + j;
            int py = p / W;
            int px = p - py * W;
            int y  = py + oy;
            int x  = px + ox;
            bReg[j] = ((unsigned)y < (unsigned)H && (unsigned)x < (unsigned)W)
                      ? src[y * W + x] : 0.f;
        }
    };
    auto put = [&](int buf) {
        As_[buf][ak2 + 0][am] = aReg.x;
        As_[buf][ak2 + 1][am] = aReg.y;
        #pragma unroll
        for (int j = 0; j < 4; j++) Bs_[buf][bk][bp4 + j] = bReg[j];
    };

    float acc[4][8];
    #pragma unroll
    for (int i = 0; i < 4; i++)
        #pragma unroll
        for (int j = 0; j < 8; j++) acc[i][j] = 0.f;

    fetch(0);
    put(0);
    __syncthreads();

    const int nK = K / 8;
    int buf = 0;
    for (int it = 0; it < nK; it++) {
        if (it + 1 < nK) fetch((it + 1) * 8);
        #pragma unroll
        for (int kk = 0; kk < 8; kk++) {
            float4 a0 = *reinterpret_cast<const float4*>(&As_[buf][kk][tr * 4]);
            float4 b0 = *reinterpret_cast<const float4*>(&Bs_[buf][kk][tc * 8]);
            float4 b1 = *reinterpret_cast<const float4*>(&Bs_[buf][kk][tc * 8 + 4]);
            float av[4] = {a0.x, a0.y, a0.z, a0.w};
            float bv[8] = {b0.x, b0.y, b0.z, b0.w, b1.x, b1.y, b1.z, b1.w};
            #pragma unroll
            for (int i = 0; i < 4; i++)
                #pragma unroll
                for (int j = 0; j < 8; j++)
                    acc[i][j] = fmaf(av[i], bv[j], acc[i][j]);
        }
        if (it + 1 < nK) put(buf ^ 1);
        __syncthreads();
        buf ^= 1;
    }

    #pragma unroll
    for (int i = 0; i < 4; i++) {
        int m = tr * 4 + i;
        float g  = bnp[m];
        float be = bnp[64 + m];
        float mu = bnp[128 + m];
        float va = bnp[192 + m];
        float scale = g * rsqrtf(va + 1e-5f);
        float shift = be - mu * scale;
        #pragma unroll
        for (int j = 0; j < 8; j++) {
            int p = bp0 + tc * 8 + j;
            float v = fmaxf(fmaf(acc[i][j], scale, shift), 0.f);
            On[(long)m * Npix + p] = v;
        }
    }
}

// ================= fp32 SGEMM (1x1 convs) ==================================
template<int TM, int DIL, bool BN, bool RELU, bool MCHECK, bool NCHECK>
__global__ void __launch_bounds__((TM/8)*16, 1)
gemm_conv(const float* __restrict__ A, const float* __restrict__ Bin,
          const float* __restrict__ bnp, float* __restrict__ Out,
          int M, int K, int H, int W, int Npix,
          long inStride, long outStride)
{
    constexpr int TN   = 128;
    constexpr int NT   = (TM / 8) * (TN / 8);
    constexpr int BVEC = (NT == 256) ? 4 : 8;

    __shared__ float As_[2][8][TM];
    __shared__ float Bs_[2][8][TN];

    const int tid = threadIdx.x;
    const int img = blockIdx.z;
    const float* Bn = Bin + (long)img * inStride;
    float*       On = Out + (long)img * outStride;
    const int bm  = blockIdx.y * TM;
    const int bp0 = blockIdx.x * TN;
    const int tr  = tid / 16;
    const int tc  = tid % 16;

    const int am = tid >> 1;
    const int ak = (tid & 1) * 4;
    const int bk = tid / (TN / BVEC);
    const int bp = (tid % (TN / BVEC)) * BVEC;

    float4 aReg;
    float  bReg[BVEC];

    auto fetch = [&](int k0) {
        int m = bm + am;
        if (!MCHECK || m < M)
            aReg = *reinterpret_cast<const float4*>(A + (long)m * K + k0 + ak);
        else
            aReg = make_float4(0.f, 0.f, 0.f, 0.f);
        int k = k0 + bk;
        if (DIL == 0) {
            const float* row = Bn + (long)k * Npix;
            if (!NCHECK) {
                #pragma unroll
                for (int j = 0; j < BVEC; j += 4) {
                    float4 v = *reinterpret_cast<const float4*>(row + bp0 + bp + j);
                    bReg[j] = v.x; bReg[j+1] = v.y; bReg[j+2] = v.z; bReg[j+3] = v.w;
                }
            } else {
                #pragma unroll
                for (int j = 0; j < BVEC; j++) {
                    int p = bp0 + bp + j;
                    bReg[j] = (p < Npix) ? row[p] : 0.f;
                }
            }
        } else {
            int cin = k / 9;
            int tap = k - cin * 9;
            int oy  = (tap / 3 - 1) * DIL;
            int ox  = (tap % 3 - 1) * DIL;
            const float* src = Bn + (long)cin * (H * W);
            #pragma unroll
            for (int j = 0; j < BVEC; j++) {
                int p  = bp0 + bp + j;
                int py = p / W;
                int px = p - py * W;
                int y  = py + oy;
                int x  = px + ox;
                bReg[j] = ((unsigned)y < (unsigned)H && (unsigned)x < (unsigned)W)
                          ? src[y * W + x] : 0.f;
            }
        }
    };
    auto put = [&](int buf) {
        As_[buf][ak + 0][am] = aReg.x;
        As_[buf][ak + 1][am] = aReg.y;
        As_[buf][ak + 2][am] = aReg.z;
        As_[buf][ak + 3][am] = aReg.w;
        #pragma unroll
        for (int j = 0; j < BVEC; j++) Bs_[buf][bk][bp + j] = bReg[j];
    };

    float acc[8][8];
    #pragma unroll
    for (int i = 0; i < 8; i++)
        #pragma unroll
        for (int j = 0; j < 8; j++) acc[i][j] = 0.f;

    fetch(0);
    put(0);
    __syncthreads();

    const int nK = K / 8;
    int buf = 0;
    for (int it = 0; it < nK; it++) {
        if (it + 1 < nK) fetch((it + 1) * 8);
        #pragma unroll
        for (int kk = 0; kk < 8; kk++) {
            float4 a0 = *reinterpret_cast<const float4*>(&As_[buf][kk][tr * 8]);
            float4 a1 = *reinterpret_cast<const float4*>(&As_[buf][kk][tr * 8 + 4]);
            float4 b0 = *reinterpret_cast<const float4*>(&Bs_[buf][kk][tc * 8]);
            float4 b1 = *reinterpret_cast<const float4*>(&Bs_[buf][kk][tc * 8 + 4]);
            float av[8] = {a0.x, a0.y, a0.z, a0.w, a1.x, a1.y, a1.z, a1.w};
            float bv[8] = {b0.x, b0.y, b0.z, b0.w, b1.x, b1.y, b1.z, b1.w};
            #pragma unroll
            for (int i = 0; i < 8; i++)
                #pragma unroll
                for (int j = 0; j < 8; j++)
                    acc[i][j] = fmaf(av[i], bv[j], acc[i][j]);
        }
        if (it + 1 < nK) put(buf ^ 1);
        __syncthreads();
        buf ^= 1;
    }

    #pragma unroll
    for (int i = 0; i < 8; i++) {
        int m = bm + tr * 8 + i;
        if (MCHECK && m >= M) continue;
        float scale = 1.f, shift = 0.f;
        if (BN) {
            float g  = bnp[m];
            float be = bnp[M + m];
            float mu = bnp[2 * M + m];
            float va = bnp[3 * M + m];
            scale = g * rsqrtf(va + 1e-5f);
            shift = be - mu * scale;
        }
        #pragma unroll
        for (int j = 0; j < 8; j++) {
            int p = bp0 + tc * 8 + j;
            if (NCHECK && p >= Npix) continue;
            float v = acc[i][j];
            if (BN)   v = fmaf(v, scale, shift);
            if (RELU) v = fmaxf(v, 0.f);
            On[(long)m * Npix + p] = v;
        }
    }
}

// -------- adaptive avg pool ------------------------------------------------
__global__ void pool_kernel(const float* __restrict__ x, float* __restrict__ pool)
{
    __shared__ float sm[2304];
    const int cin = blockIdx.x;
    const int n   = blockIdx.y;
    const float* src = x + ((long)n * 2048 + cin) * 2304;
    for (int i = threadIdx.x; i < 2304; i += blockDim.x) sm[i] = src[i];
    __syncthreads();
    int r = threadIdx.x;
    if (r < 50) {
        int sc, pi;
        if      (r < 1)  { sc = 0; pi = r; }
        else if (r < 5)  { sc = 1; pi = r - 1; }
        else if (r < 14) { sc = 2; pi = r - 5; }
        else             { sc = 3; pi = r - 14; }
        const int sides[4] = {1, 2, 3, 6};
        const int inoff[4] = {0, 2048, 10240, 28672};
        int side = sides[sc];
        int iy = pi / side, ix = pi % side;
        int bs = 48 / side;
        float s = 0.f;
        for (int yy = iy * bs; yy < (iy + 1) * bs; yy++)
            for (int xx = ix * bs; xx < (ix + 1) * bs; xx++)
                s += sm[yy * 48 + xx];
        pool[(long)n * 102400 + inoff[sc] + cin * (side * side) + pi] = s / (float)(bs * bs);
    }
}

struct PoolWArgs { const float* w[4]; const float* bn[4]; };

__global__ void pooled_conv_kernel(PoolWArgs args, const float* __restrict__ pool,
                                   float* __restrict__ ppool)
{
    int gw   = (blockIdx.x * blockDim.x + threadIdx.x) >> 5;
    int lane = threadIdx.x & 31;
    if (gw >= 51200) return;
    int n  = gw / 25600;
    int t  = gw % 25600;
    int pg = t / 512;
    int co = t % 512;
    int sc, pi;
    if      (pg < 1)  { sc = 0; pi = pg; }
    else if (pg < 5)  { sc = 1; pi = pg - 1; }
    else if (pg < 14) { sc = 2; pi = pg - 5; }
    else              { sc = 3; pi = pg - 14; }
    const int ssq[4]    = {1, 4, 9, 36};
    const int inoff[4]  = {0, 2048, 10240, 28672};
    const int outoff[4] = {0, 512, 2560, 7168};
    const float* w  = args.w[sc] + (long)co * 2048;
    const float* pb = pool + (long)n * 102400 + inoff[sc] + pi;
    int stride = ssq[sc];
    float acc = 0.f;
    for (int c = lane; c < 2048; c += 32)
        acc = fmaf(w[c], pb[(long)c * stride], acc);
    #pragma unroll
    for (int s = 16; s; s >>= 1) acc += __shfl_xor_sync(0xffffffffu, acc, s);
    if (lane == 0) {
        const float* bnp = args.bn[sc];
        float scale = bnp[co] * rsqrtf(bnp[1536 + co] + 1e-5f);
        float v = fmaf(acc, scale, bnp[512 + co] - bnp[1024 + co] * scale);
        ppool[(long)n * 25600 + outoff[sc] + co * stride + pi] = fmaxf(v, 0.f);
    }
}

// -------- assemble psp (writes HALF for the fp16 GEMM) ---------------------
__global__ void psp_assemble(const float* __restrict__ x, const float* __restrict__ ppool,
                             __half* __restrict__ psp)
{
    long idx = (long)blockIdx.x * 256 + threadIdx.x;
    if (idx >= 18874368L) return;
    int p = (int)(idx % 2304);
    long t = idx / 2304;
    int c = (int)(t % 4096);
    int n = (int)(t / 4096);
    float v;
    if (c < 2048) {
        v = x[((long)n * 2048 + c) * 2304 + p];
    } else {
        int sc = (c - 2048) >> 9;
        int cc = (c - 2048) & 511;
        const int sides[4]  = {1, 2, 3, 6};
        const int outoff[4] = {0, 512, 2560, 7168};
        int s = sides[sc];
        const float* f = ppool + (long)n * 25600 + outoff[sc] + cc * s * s;
        if (s == 1) {
            v = f[0];
        } else {
            int y = p / 48, xx = p % 48;
            float ratio = (float)(s - 1) / 47.0f;
            float sy = y * ratio, sx = xx * ratio;
            int y0 = (int)sy, x0 = (int)sx;
            if (y0 > s - 1) y0 = s - 1;
            if (x0 > s - 1) x0 = s - 1;
            int y1 = min(y0 + 1, s - 1), x1 = min(x0 + 1, s - 1);
            float wy = sy - y0, wx = sx - x0;
            float r0 = f[y0 * s + x0] * (1.f - wx) + f[y0 * s + x1] * wx;
            float r1 = f[y1 * s + x0] * (1.f - wx) + f[y1 * s + x1] * wx;
            v = r0 * (1.f - wy) + r1 * wy;
        }
    }
    psp[idx] = __float2half(v);
}

template<bool RELU>
__global__ void ups48to96(const float* __restrict__ in, float* __restrict__ out, int total)
{
    int idx = blockIdx.x * 256 + threadIdx.x;
    if (idx >= total) return;
    int p  = idx % 9216;
    int ch = idx / 9216;
    int y = p / 96, x = p % 96;
    const float r = 47.0f / 95.0f;
    float sy = y * r, sx = x * r;
    int y0 = (int)sy, x0 = (int)sx;
    if (y0 > 47) y0 = 47;
    if (x0 > 47) x0 = 47;
    int y1 = min(y0 + 1, 47), x1 = min(x0 + 1, 47);
    float wy = sy - y0, wx = sx - x0;
    const float* f = in + (long)ch * 2304;
    float v0 = f[y0 * 48 + x0] * (1.f - wx) + f[y0 * 48 + x1] * wx;
    float v1 = f[y1 * 48 + x0] * (1.f - wx) + f[y1 * 48 + x1] * wx;
    float v  = v0 * (1.f - wy) + v1 * wy;
    if (RELU) v = fmaxf(v, 0.f);
    out[idx] = v;
}

__global__ void att_kernel(const float* __restrict__ q, const float* __restrict__ kf,
                           float* __restrict__ att)
{
    int p = blockIdx.x * 256 + threadIdx.x;
    int n = blockIdx.y;
    if (p >= 9216) return;
    int y = p / 96, x = p % 96;
    int   offs[9];
    bool  valid[9];
    #pragma unroll
    for (int k = 0; k < 9; k++) {
        int yy = y + (k / 3 - 1) * 2;
        int xx = x + (k % 3 - 1) * 2;
        valid[k] = ((unsigned)yy < 96u) && ((unsigned)xx < 96u);
        offs[k]  = valid[k] ? yy * 96 + xx : 0;
    }
    float e[9];
    #pragma unroll
    for (int k = 0; k < 9; k++) e[k] = 0.f;
    const float* qn = q  + (long)n * 64 * 9216;
    const float* kn = kf + (long)n * 64 * 9216;
    for (int c = 0; c < 64; c++) {
        float qv = qn[c * 9216 + p];
        const float* base = kn + c * 9216;
        #pragma unroll
        for (int k = 0; k < 9; k++) {
            float kv = valid[k] ? base[offs[k]] : 0.f;
            e[k] = fmaf(qv, kv, e[k]);
        }
    }
    float mx = e[0];
    #pragma unroll
    for (int k = 1; k < 9; k++) mx = fmaxf(mx, e[k]);
    float sum = 0.f;
    #pragma unroll
    for (int k = 0; k < 9; k++) { e[k] = __expf(e[k] - mx); sum += e[k]; }
    float inv = 1.f / sum;
    #pragma unroll
    for (int k = 0; k < 9; k++)
        att[(long)n * 82944 + k * 9216 + p] = e[k] * inv;
}

__global__ void final_kernel(const float* __restrict__ att, const float* __restrict__ z,
                             const float* __restrict__ bias, float* __restrict__ out)
{
    int p = blockIdx.x * 256 + threadIdx.x;
    int o = blockIdx.y;
    int n = blockIdx.z;
    if (p >= 9216) return;
    int y = p / 96, x = p % 96;
    const float* zr = z   + ((long)n * 59 + o) * 9216;
    const float* an = att + (long)n * 82944;
    float acc = bias[o];
    #pragma unroll
    for (int k = 0; k < 9; k++) {
        int yy = y + (k / 3 - 1) * 2;
        int xx = x + (k % 3 - 1) * 2;
        float zv = ((unsigned)yy < 96u && (unsigned)xx < 96u) ? zr[yy * 96 + xx] : 0.f;
        acc = fmaf(an[k * 9216 + p], zv, acc);
    }
    out[((long)n * 59 + o) * 9216 + p] = acc;
}

// ---------------------------------------------------------------------------
extern "C" void kernel_launch(void* const* d_in, const int* in_sizes, int n_in,
                              void* d_out, int out_size)
{
    (void)in_sizes; (void)n_in; (void)out_size;
    const float* c1    = (const float*)d_in[0];
    const float* c2    = (const float*)d_in[1];
    const float* x     = (const float*)d_in[2];
    const float* w_r1  = (const float*)d_in[3];
    const float* bnr1  = (const float*)d_in[4];
    const float* w_r2  = (const float*)d_in[5];
    const float* bnr2  = (const float*)d_in[6];
    const float* w_r3  = (const float*)d_in[7];
    const float* bnr3  = (const float*)d_in[8];
    const float* w_c5  = (const float*)d_in[17];
    const float* bnc5  = (const float*)d_in[18];
    const float* w_c6  = (const float*)d_in[19];
    const float* b_c6  = (const float*)d_in[20];

    float *r1p, *r2p, *t48p, *c2rp, *attp, *poolp, *ppolp, *o5p, *z48p, *z96p;
    __half *psphp, *w5hp;
    cudaGetSymbolAddress((void**)&r1p,  g_r1b);
    cudaGetSymbolAddress((void**)&r2p,  g_r2b);
    cudaGetSymbolAddress((void**)&t48p, g_t48);
    cudaGetSymbolAddress((void**)&c2rp, g_c2r);
    cudaGetSymbolAddress((void**)&attp, g_attb);
    cudaGetSymbolAddress((void**)&poolp, g_pool);
    cudaGetSymbolAddress((void**)&ppolp, g_ppol);
    cudaGetSymbolAddress((void**)&psphp, g_psph);
    cudaGetSymbolAddress((void**)&o5p,  g_out5);
    cudaGetSymbolAddress((void**)&z48p, g_z48);
    cudaGetSymbolAddress((void**)&z96p, g_z96);
    cudaGetSymbolAddress((void**)&w5hp, g_w5h);

    const int c5_smem = 2 * HBUF * sizeof(__half);  // 73728 B
    cudaFuncSetAttribute(c5_mma_kernel, cudaFuncAttributeMaxDynamicSharedMemorySize, c5_smem);

    // 1: convert c5 weights to half
    w2h_kernel<<<18432, 256>>>(w_c5, w5hp);
    // 2..4: pyramid pooling chain -> psp (half)
    pool_kernel<<<dim3(2048, 2), 64>>>(x, poolp);
    PoolWArgs pa;
    pa.w[0] = (const float*)d_in[9];  pa.bn[0] = (const float*)d_in[10];
    pa.w[1] = (const float*)d_in[11]; pa.bn[1] = (const float*)d_in[12];
    pa.w[2] = (const float*)d_in[13]; pa.bn[2] = (const float*)d_in[14];
    pa.w[3] = (const float*)d_in[15]; pa.bn[3] = (const float*)d_in[16];
    pooled_conv_kernel<<<6400, 256>>>(pa, poolp, ppolp);
    psp_assemble<<<73728, 256>>>(x, ppolp, psphp);
    // 5: query conv1
    gemm_conv64<2><<<dim3(72, 1, 2), 256>>>(w_r1, c1, bnr1, r1p, 2304, 96, 96, 256L * 9216);
    // 6: conv5 on tensor cores (fp16 + ldmatrix)
    c5_mma_kernel<<<dim3(18, 4, 2), 512, c5_smem>>>(w5hp, psphp, bnc5, o5p);
    // 7: query conv2
    gemm_conv64<2><<<dim3(72, 1, 2), 256>>>(w_r2, r1p, bnr2, r2p, 576, 96, 96, 64L * 9216);
    // 8..10: key branch + attention
    gemm_conv<64, 0, true, false, false, false><<<dim3(18, 1, 2), 128>>>(
        w_r3, c2, bnr3, t48p, 64, 512, 48, 48, 2304, 512L * 2304, 64L * 2304);
    ups48to96<true><<<4608, 256>>>(t48p, c2rp, 2 * 64 * 9216);
    att_kernel<<<dim3(36, 2), 256>>>(r2p, c2rp, attp);
    // 11..13: conv6 (pre-upsample) + aggregate
    gemm_conv<64, 0, false, false, true, false><<<dim3(18, 1, 2), 128>>>(
        w_c6, o5p, nullptr, z48p, 59, 512, 48, 48, 2304, 512L * 2304, 59L * 2304);
    ups48to96<false><<<4248, 256>>>(z48p, z96p, 2 * 59 * 9216);
    final_kernel<<<dim3(36, 59, 2), 256>>>(attp, z96p, b_c6, (float*)d_out);
}